// round 4
// baseline (speedup 1.0000x reference)
#include <cuda_runtime.h>
#include <cuda_bf16.h>

#define NN 100000

// Scratch (device globals — no allocation allowed)
__device__ __align__(16) float g_y[2][NN * 16];     // x @ w_nbr        (layer-1 neighbor proj)
__device__ __align__(16) float g_agg1[2][NN * 16];  // init x@w_self+b, then += segsum(y[src])
__device__ __align__(16) float g_h1[2][NN * 16];    // relu(agg1)
__device__ __align__(16) float g_agg2[2][NN * 16];  // init 0, then += segsum(h1[src])
__device__ __align__(16) float g_mol[NN * 100];     // concat(p, l)

__device__ __forceinline__ void atomicAddF4(float4* p, float4 v) {
#if defined(__CUDA_ARCH__) && __CUDA_ARCH__ >= 900
    atomicAdd(p, v);
#else
    float* f = (float*)p;
    atomicAdd(f + 0, v.x);
    atomicAdd(f + 1, v.y);
    atomicAdd(f + 2, v.z);
    atomicAdd(f + 3, v.w);
#endif
}

// ---------------------------------------------------------------------------
// Kernel 1: fused layer-1 projection.
//   y    = x @ w_nbr                      [N,16]
//   agg1 = x @ w_self + b   (initializer) [N,16]
//   agg2 = 0                (initializer) [N,16]
// Block: 256 threads, 32 rows/block. x tile + both weights staged in smem.
// ---------------------------------------------------------------------------
__global__ void proj_kernel(const float* __restrict__ x,
                            const float* __restrict__ w_self,
                            const float* __restrict__ w_nbr,
                            const float* __restrict__ bias,
                            int b, int N) {
    __shared__ __align__(16) float xs[32][128];
    __shared__ __align__(16) float ws[128][32];  // cols 0-15: w_nbr, 16-31: w_self
    int t = threadIdx.x;

    for (int i = t; i < 2048; i += 256) {
        int k = i >> 4, o = i & 15;
        ws[k][o] = w_nbr[i];
        ws[k][o + 16] = w_self[i];
    }

    int row0 = blockIdx.x << 5;
    const float4* x4 = (const float4*)x;
    float4* xs4 = (float4*)xs;
    int base = row0 * 32;  // row = 32 float4
    int lim = N * 32;
    for (int i = t; i < 1024; i += 256) {
        int g = base + i;
        xs4[i] = (g < lim) ? x4[g] : make_float4(0.f, 0.f, 0.f, 0.f);
    }
    __syncthreads();

    int og = (t & 7) << 2;  // output group (0..28 step 4)
    int r = t >> 3;         // row in tile (0..31)
    float4 acc = make_float4(0.f, 0.f, 0.f, 0.f);
#pragma unroll 32
    for (int k = 0; k < 128; k++) {
        float xv = xs[r][k];
        float4 wv = *(const float4*)&ws[k][og];
        acc.x = fmaf(xv, wv.x, acc.x);
        acc.y = fmaf(xv, wv.y, acc.y);
        acc.z = fmaf(xv, wv.z, acc.z);
        acc.w = fmaf(xv, wv.w, acc.w);
    }

    int row = row0 + r;
    if (row < N) {
        if (og < 16) {
            *(float4*)(g_y[b] + row * 16 + og) = acc;
            *(float4*)(g_agg2[b] + row * 16 + og) = make_float4(0.f, 0.f, 0.f, 0.f);
        } else {
            int o = og - 16;
            float4 bb = *(const float4*)(bias + o);
            acc.x += bb.x; acc.y += bb.y; acc.z += bb.z; acc.w += bb.w;
            *(float4*)(g_agg1[b] + row * 16 + o) = acc;
        }
    }
}

// ---------------------------------------------------------------------------
// Kernel 2: edge aggregation (scatter-add), 4 threads per edge (16B each).
// Gather source & scatter dest are 6.4MB each -> L2 resident.
// ---------------------------------------------------------------------------
__global__ void agg_kernel(const int* __restrict__ src,
                           const int* __restrict__ dst,
                           int b, int layer, int E) {
    int i = blockIdx.x * blockDim.x + threadIdx.x;
    int e = i >> 2;
    if (e >= E) return;
    int q = (i & 3) << 2;
    int s = __ldg(src + e);
    int d = __ldg(dst + e);
    const float* v = layer ? g_h1[b] : g_y[b];
    float* agg = layer ? g_agg2[b] : g_agg1[b];
    float4 val = *(const float4*)(v + s * 16 + q);
    atomicAddF4((float4*)(agg + d * 16 + q), val);
}

// ---------------------------------------------------------------------------
// Kernel 3: h1 = relu(agg1)   (agg1 already holds self-term + bias + agg)
// ---------------------------------------------------------------------------
__global__ void relu_kernel(int b, int n4) {
    int i = blockIdx.x * blockDim.x + threadIdx.x;
    if (i >= n4) return;
    float4 v = ((const float4*)g_agg1[b])[i];
    v.x = fmaxf(v.x, 0.f);
    v.y = fmaxf(v.y, 0.f);
    v.z = fmaxf(v.z, 0.f);
    v.w = fmaxf(v.w, 0.f);
    ((float4*)g_h1[b])[i] = v;
}

// ---------------------------------------------------------------------------
// Kernel 4: layer-2 conv output.
//   mol[:, col0:col0+50] = h1 @ w_s + agg2 @ w_n + b
// Block: 256 threads = 4 rows x 64 lanes (50 active outputs).
// ---------------------------------------------------------------------------
__global__ void layer2_kernel(int b,
                              const float* __restrict__ w_s,
                              const float* __restrict__ w_n,
                              const float* __restrict__ bias,
                              int col0, int N) {
    __shared__ float hs[4][16];
    __shared__ float as_[4][16];
    __shared__ float ws1[16 * 50];
    __shared__ float ws2[16 * 50];
    __shared__ float bs[50];
    int t = threadIdx.x;
    for (int i = t; i < 800; i += 256) {
        ws1[i] = w_s[i];
        ws2[i] = w_n[i];
    }
    if (t < 50) bs[t] = bias[t];

    int row0 = blockIdx.x << 2;
    if (t < 64) {
        int r = t >> 4, k = t & 15;
        int row = row0 + r;
        hs[r][k] = (row < N) ? g_h1[b][row * 16 + k] : 0.f;
    } else if (t < 128) {
        int tt = t - 64;
        int r = tt >> 4, k = tt & 15;
        int row = row0 + r;
        as_[r][k] = (row < N) ? g_agg2[b][row * 16 + k] : 0.f;
    }
    __syncthreads();

    int o = t & 63;
    int r = t >> 6;
    int row = row0 + r;
    if (o < 50 && row < N) {
        float acc = bs[o];
#pragma unroll
        for (int k = 0; k < 16; k++) {
            acc = fmaf(hs[r][k], ws1[k * 50 + o], acc);
            acc = fmaf(as_[r][k], ws2[k * 50 + o], acc);
        }
        g_mol[row * 100 + col0 + o] = acc;
    }
}

// ---------------------------------------------------------------------------
// Kernel 5: MLP head. One thread per row; row (100 floats) in registers,
// all weights in smem (w_in transposed to [60][25] float4 for LDS.128
// uniform-broadcast reads).
// ---------------------------------------------------------------------------
__global__ __launch_bounds__(128)
void head_kernel(const float* __restrict__ action,
                 const float* __restrict__ w_in, const float* __restrict__ b_in,
                 const float* __restrict__ w_hid, const float* __restrict__ b_hid,
                 const float* __restrict__ w_out, const float* __restrict__ b_out,
                 float* __restrict__ out, int N) {
    __shared__ float4 wst[60 * 25];  // transposed w_in: [o][kk] -> 4 k-values
    __shared__ float wh[700];
    __shared__ float bi[60];
    __shared__ float bh[10];
    __shared__ float wo[10];
    __shared__ float bo;
    int t = threadIdx.x;
    for (int i = t; i < 1500; i += 128) {
        int o = i / 25, kk = i % 25;
        float4 v;
        v.x = w_in[(kk * 4 + 0) * 60 + o];
        v.y = w_in[(kk * 4 + 1) * 60 + o];
        v.z = w_in[(kk * 4 + 2) * 60 + o];
        v.w = w_in[(kk * 4 + 3) * 60 + o];
        wst[i] = v;
    }
    for (int i = t; i < 700; i += 128) wh[i] = w_hid[i];
    if (t < 60) bi[t] = b_in[t];
    if (t < 10) { bh[t] = b_hid[t]; wo[t] = w_out[t]; }
    if (t == 0) bo = b_out[0];
    __syncthreads();

    int row = blockIdx.x * 128 + t;
    if (row >= N) return;

    float4 xr[25];
    const float4* m4 = (const float4*)(g_mol + (size_t)row * 100);
#pragma unroll
    for (int i = 0; i < 25; i++) xr[i] = m4[i];

    float pol[10];
#pragma unroll
    for (int a = 0; a < 10; a++) pol[a] = bh[a];

    for (int o = 0; o < 60; o++) {
        float acc = bi[o];
        const float4* wc = wst + o * 25;
#pragma unroll
        for (int kk = 0; kk < 25; kk++) {
            float4 w4 = wc[kk];
            acc = fmaf(xr[kk].x, w4.x, acc);
            acc = fmaf(xr[kk].y, w4.y, acc);
            acc = fmaf(xr[kk].z, w4.z, acc);
            acc = fmaf(xr[kk].w, w4.w, acc);
        }
        float f = fmaxf(acc, 0.f);
#pragma unroll
        for (int a = 0; a < 10; a++) pol[a] = fmaf(f, wh[o * 10 + a], pol[a]);
    }

    const float* arow = action + (size_t)row * 10;
#pragma unroll
    for (int j = 0; j < 10; j++) {
        float av = arow[j];
#pragma unroll
        for (int a = 0; a < 10; a++) pol[a] = fmaf(av, wh[(60 + j) * 10 + a], pol[a]);
    }

    float res = bo;
#pragma unroll
    for (int a = 0; a < 10; a++) res = fmaf(fmaxf(pol[a], 0.f), wo[a], res);
    out[row] = res;
}

// ---------------------------------------------------------------------------
extern "C" void kernel_launch(void* const* d_in, const int* in_sizes, int n_in,
                              void* d_out, int out_size) {
    const float* px = (const float*)d_in[0];
    const int*   pe = (const int*)d_in[1];
    const float* lx = (const float*)d_in[2];
    const int*   le = (const int*)d_in[3];
    const float* action = (const float*)d_in[4];
    const float* wp1s = (const float*)d_in[5];
    const float* wp1n = (const float*)d_in[6];
    const float* bp1  = (const float*)d_in[7];
    const float* wp2s = (const float*)d_in[8];
    const float* wp2n = (const float*)d_in[9];
    const float* bp2  = (const float*)d_in[10];
    const float* wl1s = (const float*)d_in[11];
    const float* wl1n = (const float*)d_in[12];
    const float* bl1  = (const float*)d_in[13];
    const float* wl2s = (const float*)d_in[14];
    const float* wl2n = (const float*)d_in[15];
    const float* bl2  = (const float*)d_in[16];
    const float* w_in  = (const float*)d_in[17];
    const float* b_in  = (const float*)d_in[18];
    const float* w_hid = (const float*)d_in[19];
    const float* b_hid = (const float*)d_in[20];
    const float* w_out = (const float*)d_in[21];
    const float* b_out = (const float*)d_in[22];
    float* out = (float*)d_out;

    int N = in_sizes[0] / 128;
    int Es[2] = {in_sizes[1] / 2, in_sizes[3] / 2};
    const float* xs[2] = {px, lx};
    const int* es[2] = {pe, le};
    const float* w1s[2] = {wp1s, wl1s};
    const float* w1n[2] = {wp1n, wl1n};
    const float* b1[2]  = {bp1, bl1};
    const float* w2s[2] = {wp2s, wl2s};
    const float* w2n[2] = {wp2n, wl2n};
    const float* b2[2]  = {bp2, bl2};

    for (int b = 0; b < 2; b++) {
        int E = Es[b];
        proj_kernel<<<(N + 31) / 32, 256>>>(xs[b], w1s[b], w1n[b], b1[b], b, N);
        agg_kernel<<<(E * 4 + 255) / 256, 256>>>(es[b], es[b] + E, b, 0, E);
        relu_kernel<<<(N * 4 + 255) / 256, 256>>>(b, N * 4);
        agg_kernel<<<(E * 4 + 255) / 256, 256>>>(es[b], es[b] + E, b, 1, E);
        layer2_kernel<<<(N + 3) / 4, 256>>>(b, w2s[b], w2n[b], b2[b], 50 * b, N);
    }
    head_kernel<<<(N + 127) / 128, 128>>>(action, w_in, b_in, w_hid, b_hid,
                                          w_out, b_out, out, N);
}

// round 5
// speedup vs baseline: 1.0458x; 1.0458x over previous
#include <cuda_runtime.h>
#include <cuda_bf16.h>

#define NN 100000

// Scratch (device globals — no allocation allowed)
__device__ __align__(16) float g_y[2][NN * 16];     // x @ w_nbr        (layer-1 neighbor proj)
__device__ __align__(16) float g_agg1[2][NN * 16];  // init x@w_self+b, then += segsum(y[src])
__device__ __align__(16) float g_h1[2][NN * 16];    // relu(agg1)
__device__ __align__(16) float g_agg2[2][NN * 16];  // init 0, then += segsum(h1[src])
__device__ __align__(16) float g_mol[NN * 100];     // concat(p, l)

__device__ __forceinline__ void atomicAddF4(float4* p, float4 v) {
#if defined(__CUDA_ARCH__) && __CUDA_ARCH__ >= 900
    atomicAdd(p, v);
#else
    float* f = (float*)p;
    atomicAdd(f + 0, v.x);
    atomicAdd(f + 1, v.y);
    atomicAdd(f + 2, v.z);
    atomicAdd(f + 3, v.w);
#endif
}

// ---------------------------------------------------------------------------
// Kernel 1: fused layer-1 projection.
//   y    = x @ w_nbr                      [N,16]
//   agg1 = x @ w_self + b   (initializer) [N,16]
//   agg2 = 0                (initializer) [N,16]
// Block: 256 threads, 32 rows/block. x tile + both weights staged in smem.
// ---------------------------------------------------------------------------
__global__ void proj_kernel(const float* __restrict__ x,
                            const float* __restrict__ w_self,
                            const float* __restrict__ w_nbr,
                            const float* __restrict__ bias,
                            int b, int N) {
    __shared__ __align__(16) float xs[32][128];
    __shared__ __align__(16) float ws[128][32];  // cols 0-15: w_nbr, 16-31: w_self
    int t = threadIdx.x;

    for (int i = t; i < 2048; i += 256) {
        int k = i >> 4, o = i & 15;
        ws[k][o] = w_nbr[i];
        ws[k][o + 16] = w_self[i];
    }

    int row0 = blockIdx.x << 5;
    const float4* x4 = (const float4*)x;
    float4* xs4 = (float4*)xs;
    int base = row0 * 32;  // row = 32 float4
    int lim = N * 32;
    for (int i = t; i < 1024; i += 256) {
        int g = base + i;
        xs4[i] = (g < lim) ? x4[g] : make_float4(0.f, 0.f, 0.f, 0.f);
    }
    __syncthreads();

    int og = (t & 7) << 2;  // output group (0..28 step 4)
    int r = t >> 3;         // row in tile (0..31)
    float4 acc = make_float4(0.f, 0.f, 0.f, 0.f);
#pragma unroll 32
    for (int k = 0; k < 128; k++) {
        float xv = xs[r][k];
        float4 wv = *(const float4*)&ws[k][og];
        acc.x = fmaf(xv, wv.x, acc.x);
        acc.y = fmaf(xv, wv.y, acc.y);
        acc.z = fmaf(xv, wv.z, acc.z);
        acc.w = fmaf(xv, wv.w, acc.w);
    }

    int row = row0 + r;
    if (row < N) {
        if (og < 16) {
            *(float4*)(g_y[b] + row * 16 + og) = acc;
            *(float4*)(g_agg2[b] + row * 16 + og) = make_float4(0.f, 0.f, 0.f, 0.f);
        } else {
            int o = og - 16;
            float4 bb = *(const float4*)(bias + o);
            acc.x += bb.x; acc.y += bb.y; acc.z += bb.z; acc.w += bb.w;
            *(float4*)(g_agg1[b] + row * 16 + o) = acc;
        }
    }
}

// ---------------------------------------------------------------------------
// Kernel 2: edge aggregation (scatter-add), 4 threads per edge (16B each).
// Gather source & scatter dest are 6.4MB each -> L2 resident.
// ---------------------------------------------------------------------------
__global__ void agg_kernel(const int* __restrict__ src,
                           const int* __restrict__ dst,
                           int b, int layer, int E) {
    int i = blockIdx.x * blockDim.x + threadIdx.x;
    int e = i >> 2;
    if (e >= E) return;
    int q = (i & 3) << 2;
    int s = __ldg(src + e);
    int d = __ldg(dst + e);
    const float* v = layer ? g_h1[b] : g_y[b];
    float* agg = layer ? g_agg2[b] : g_agg1[b];
    float4 val = *(const float4*)(v + s * 16 + q);
    atomicAddF4((float4*)(agg + d * 16 + q), val);
}

// ---------------------------------------------------------------------------
// Kernel 3: h1 = relu(agg1)   (agg1 already holds self-term + bias + agg)
// ---------------------------------------------------------------------------
__global__ void relu_kernel(int b, int n4) {
    int i = blockIdx.x * blockDim.x + threadIdx.x;
    if (i >= n4) return;
    float4 v = ((const float4*)g_agg1[b])[i];
    v.x = fmaxf(v.x, 0.f);
    v.y = fmaxf(v.y, 0.f);
    v.z = fmaxf(v.z, 0.f);
    v.w = fmaxf(v.w, 0.f);
    ((float4*)g_h1[b])[i] = v;
}

// ---------------------------------------------------------------------------
// Kernel 4: layer-2 conv output.
//   mol[:, col0:col0+50] = h1 @ w_s + agg2 @ w_n + b
// Block: 256 threads = 4 rows x 64 lanes (50 active outputs).
// ---------------------------------------------------------------------------
__global__ void layer2_kernel(int b,
                              const float* __restrict__ w_s,
                              const float* __restrict__ w_n,
                              const float* __restrict__ bias,
                              int col0, int N) {
    __shared__ float hs[4][16];
    __shared__ float as_[4][16];
    __shared__ float ws1[16 * 50];
    __shared__ float ws2[16 * 50];
    __shared__ float bs[50];
    int t = threadIdx.x;
    for (int i = t; i < 800; i += 256) {
        ws1[i] = w_s[i];
        ws2[i] = w_n[i];
    }
    if (t < 50) bs[t] = bias[t];

    int row0 = blockIdx.x << 2;
    if (t < 64) {
        int r = t >> 4, k = t & 15;
        int row = row0 + r;
        hs[r][k] = (row < N) ? g_h1[b][row * 16 + k] : 0.f;
    } else if (t < 128) {
        int tt = t - 64;
        int r = tt >> 4, k = tt & 15;
        int row = row0 + r;
        as_[r][k] = (row < N) ? g_agg2[b][row * 16 + k] : 0.f;
    }
    __syncthreads();

    int o = t & 63;
    int r = t >> 6;
    int row = row0 + r;
    if (o < 50 && row < N) {
        float acc = bs[o];
#pragma unroll
        for (int k = 0; k < 16; k++) {
            acc = fmaf(hs[r][k], ws1[k * 50 + o], acc);
            acc = fmaf(as_[r][k], ws2[k * 50 + o], acc);
        }
        g_mol[row * 100 + col0 + o] = acc;
    }
}

// ---------------------------------------------------------------------------
// Kernel 5: MLP head. One thread per row; row (100 floats) in registers,
// all weights in smem (w_in transposed to [60][25] float4 for LDS.128
// uniform-broadcast reads).
// ---------------------------------------------------------------------------
__global__ __launch_bounds__(128)
void head_kernel(const float* __restrict__ action,
                 const float* __restrict__ w_in, const float* __restrict__ b_in,
                 const float* __restrict__ w_hid, const float* __restrict__ b_hid,
                 const float* __restrict__ w_out, const float* __restrict__ b_out,
                 float* __restrict__ out, int N) {
    __shared__ float4 wst[60 * 25];  // transposed w_in: [o][kk] -> 4 k-values
    __shared__ float wh[700];
    __shared__ float bi[60];
    __shared__ float bh[10];
    __shared__ float wo[10];
    __shared__ float bo;
    int t = threadIdx.x;
    for (int i = t; i < 1500; i += 128) {
        int o = i / 25, kk = i % 25;
        float4 v;
        v.x = w_in[(kk * 4 + 0) * 60 + o];
        v.y = w_in[(kk * 4 + 1) * 60 + o];
        v.z = w_in[(kk * 4 + 2) * 60 + o];
        v.w = w_in[(kk * 4 + 3) * 60 + o];
        wst[i] = v;
    }
    for (int i = t; i < 700; i += 128) wh[i] = w_hid[i];
    if (t < 60) bi[t] = b_in[t];
    if (t < 10) { bh[t] = b_hid[t]; wo[t] = w_out[t]; }
    if (t == 0) bo = b_out[0];
    __syncthreads();

    int row = blockIdx.x * 128 + t;
    if (row >= N) return;

    float4 xr[25];
    const float4* m4 = (const float4*)(g_mol + (size_t)row * 100);
#pragma unroll
    for (int i = 0; i < 25; i++) xr[i] = m4[i];

    float pol[10];
#pragma unroll
    for (int a = 0; a < 10; a++) pol[a] = bh[a];

    for (int o = 0; o < 60; o++) {
        float acc = bi[o];
        const float4* wc = wst + o * 25;
#pragma unroll
        for (int kk = 0; kk < 25; kk++) {
            float4 w4 = wc[kk];
            acc = fmaf(xr[kk].x, w4.x, acc);
            acc = fmaf(xr[kk].y, w4.y, acc);
            acc = fmaf(xr[kk].z, w4.z, acc);
            acc = fmaf(xr[kk].w, w4.w, acc);
        }
        float f = fmaxf(acc, 0.f);
#pragma unroll
        for (int a = 0; a < 10; a++) pol[a] = fmaf(f, wh[o * 10 + a], pol[a]);
    }

    const float* arow = action + (size_t)row * 10;
#pragma unroll
    for (int j = 0; j < 10; j++) {
        float av = arow[j];
#pragma unroll
        for (int a = 0; a < 10; a++) pol[a] = fmaf(av, wh[(60 + j) * 10 + a], pol[a]);
    }

    float res = bo;
#pragma unroll
    for (int a = 0; a < 10; a++) res = fmaf(fmaxf(pol[a], 0.f), wo[a], res);
    out[row] = res;
}

// ---------------------------------------------------------------------------
extern "C" void kernel_launch(void* const* d_in, const int* in_sizes, int n_in,
                              void* d_out, int out_size) {
    const float* px = (const float*)d_in[0];
    const int*   pe = (const int*)d_in[1];
    const float* lx = (const float*)d_in[2];
    const int*   le = (const int*)d_in[3];
    const float* action = (const float*)d_in[4];
    const float* wp1s = (const float*)d_in[5];
    const float* wp1n = (const float*)d_in[6];
    const float* bp1  = (const float*)d_in[7];
    const float* wp2s = (const float*)d_in[8];
    const float* wp2n = (const float*)d_in[9];
    const float* bp2  = (const float*)d_in[10];
    const float* wl1s = (const float*)d_in[11];
    const float* wl1n = (const float*)d_in[12];
    const float* bl1  = (const float*)d_in[13];
    const float* wl2s = (const float*)d_in[14];
    const float* wl2n = (const float*)d_in[15];
    const float* bl2  = (const float*)d_in[16];
    const float* w_in  = (const float*)d_in[17];
    const float* b_in  = (const float*)d_in[18];
    const float* w_hid = (const float*)d_in[19];
    const float* b_hid = (const float*)d_in[20];
    const float* w_out = (const float*)d_in[21];
    const float* b_out = (const float*)d_in[22];
    float* out = (float*)d_out;

    int N = in_sizes[0] / 128;
    int Es[2] = {in_sizes[1] / 2, in_sizes[3] / 2};
    const float* xs[2] = {px, lx};
    const int* es[2] = {pe, le};
    const float* w1s[2] = {wp1s, wl1s};
    const float* w1n[2] = {wp1n, wl1n};
    const float* b1[2]  = {bp1, bl1};
    const float* w2s[2] = {wp2s, wl2s};
    const float* w2n[2] = {wp2n, wl2n};
    const float* b2[2]  = {bp2, bl2};

    for (int b = 0; b < 2; b++) {
        int E = Es[b];
        proj_kernel<<<(N + 31) / 32, 256>>>(xs[b], w1s[b], w1n[b], b1[b], b, N);
        agg_kernel<<<(E * 4 + 255) / 256, 256>>>(es[b], es[b] + E, b, 0, E);
        relu_kernel<<<(N * 4 + 255) / 256, 256>>>(b, N * 4);
        agg_kernel<<<(E * 4 + 255) / 256, 256>>>(es[b], es[b] + E, b, 1, E);
        layer2_kernel<<<(N + 3) / 4, 256>>>(b, w2s[b], w2n[b], b2[b], 50 * b, N);
    }
    head_kernel<<<(N + 127) / 128, 128>>>(action, w_in, b_in, w_hid, b_hid,
                                          w_out, b_out, out, N);
}

// round 6
// speedup vs baseline: 1.0469x; 1.0011x over previous
#include <cuda_runtime.h>
#include <cuda_bf16.h>

#define NN 100000

// Scratch (device globals — no allocation allowed)
__device__ __align__(16) float g_y[2][NN * 16];     // x @ w_nbr        (layer-1 neighbor proj)
__device__ __align__(16) float g_agg1[2][NN * 16];  // init x@w_self+b, then += segsum(y[src])
__device__ __align__(16) float g_h1[2][NN * 16];    // relu(agg1)
__device__ __align__(16) float g_agg2[2][NN * 16];  // init 0, then += segsum(h1[src])
__device__ __align__(16) float g_mol[NN * 100];     // concat(p, l)

__device__ __forceinline__ void atomicAddF4(float4* p, float4 v) {
#if defined(__CUDA_ARCH__) && __CUDA_ARCH__ >= 900
    atomicAdd(p, v);
#else
    float* f = (float*)p;
    atomicAdd(f + 0, v.x);
    atomicAdd(f + 1, v.y);
    atomicAdd(f + 2, v.z);
    atomicAdd(f + 3, v.w);
#endif
}

// ---------------------------------------------------------------------------
// Kernel 1: fused layer-1 projection.
//   y    = x @ w_nbr                      [N,16]
//   agg1 = x @ w_self + b   (initializer) [N,16]
//   agg2 = 0                (initializer) [N,16]
// Block: 256 threads, 32 rows/block. x tile + both weights staged in smem.
// ---------------------------------------------------------------------------
__global__ void proj_kernel(const float* __restrict__ x,
                            const float* __restrict__ w_self,
                            const float* __restrict__ w_nbr,
                            const float* __restrict__ bias,
                            int b, int N) {
    __shared__ __align__(16) float xs[32][128];
    __shared__ __align__(16) float ws[128][32];  // cols 0-15: w_nbr, 16-31: w_self
    int t = threadIdx.x;

    for (int i = t; i < 2048; i += 256) {
        int k = i >> 4, o = i & 15;
        ws[k][o] = w_nbr[i];
        ws[k][o + 16] = w_self[i];
    }

    int row0 = blockIdx.x << 5;
    const float4* x4 = (const float4*)x;
    float4* xs4 = (float4*)xs;
    int base = row0 * 32;  // row = 32 float4
    int lim = N * 32;
    for (int i = t; i < 1024; i += 256) {
        int g = base + i;
        xs4[i] = (g < lim) ? x4[g] : make_float4(0.f, 0.f, 0.f, 0.f);
    }
    __syncthreads();

    int og = (t & 7) << 2;  // output group (0..28 step 4)
    int r = t >> 3;         // row in tile (0..31)
    float4 acc = make_float4(0.f, 0.f, 0.f, 0.f);
#pragma unroll 32
    for (int k = 0; k < 128; k++) {
        float xv = xs[r][k];
        float4 wv = *(const float4*)&ws[k][og];
        acc.x = fmaf(xv, wv.x, acc.x);
        acc.y = fmaf(xv, wv.y, acc.y);
        acc.z = fmaf(xv, wv.z, acc.z);
        acc.w = fmaf(xv, wv.w, acc.w);
    }

    int row = row0 + r;
    if (row < N) {
        if (og < 16) {
            *(float4*)(g_y[b] + row * 16 + og) = acc;
            *(float4*)(g_agg2[b] + row * 16 + og) = make_float4(0.f, 0.f, 0.f, 0.f);
        } else {
            int o = og - 16;
            float4 bb = *(const float4*)(bias + o);
            acc.x += bb.x; acc.y += bb.y; acc.z += bb.z; acc.w += bb.w;
            *(float4*)(g_agg1[b] + row * 16 + o) = acc;
        }
    }
}

// ---------------------------------------------------------------------------
// Kernel 2: edge aggregation (scatter-add), 4 threads per edge (16B each).
// Gather source & scatter dest are 6.4MB each -> L2 resident.
// ---------------------------------------------------------------------------
__global__ void agg_kernel(const int* __restrict__ src,
                           const int* __restrict__ dst,
                           int b, int layer, int E) {
    int i = blockIdx.x * blockDim.x + threadIdx.x;
    int e = i >> 2;
    if (e >= E) return;
    int q = (i & 3) << 2;
    int s = __ldg(src + e);
    int d = __ldg(dst + e);
    const float* v = layer ? g_h1[b] : g_y[b];
    float* agg = layer ? g_agg2[b] : g_agg1[b];
    float4 val = *(const float4*)(v + s * 16 + q);
    atomicAddF4((float4*)(agg + d * 16 + q), val);
}

// ---------------------------------------------------------------------------
// Kernel 3: h1 = relu(agg1)   (agg1 already holds self-term + bias + agg)
// ---------------------------------------------------------------------------
__global__ void relu_kernel(int b, int n4) {
    int i = blockIdx.x * blockDim.x + threadIdx.x;
    if (i >= n4) return;
    float4 v = ((const float4*)g_agg1[b])[i];
    v.x = fmaxf(v.x, 0.f);
    v.y = fmaxf(v.y, 0.f);
    v.z = fmaxf(v.z, 0.f);
    v.w = fmaxf(v.w, 0.f);
    ((float4*)g_h1[b])[i] = v;
}

// ---------------------------------------------------------------------------
// Kernel 4: layer-2 conv output.
//   mol[:, col0:col0+50] = h1 @ w_s + agg2 @ w_n + b
// Block: 256 threads = 4 rows x 64 lanes (50 active outputs).
// ---------------------------------------------------------------------------
__global__ void layer2_kernel(int b,
                              const float* __restrict__ w_s,
                              const float* __restrict__ w_n,
                              const float* __restrict__ bias,
                              int col0, int N) {
    __shared__ float hs[4][16];
    __shared__ float as_[4][16];
    __shared__ float ws1[16 * 50];
    __shared__ float ws2[16 * 50];
    __shared__ float bs[50];
    int t = threadIdx.x;
    for (int i = t; i < 800; i += 256) {
        ws1[i] = w_s[i];
        ws2[i] = w_n[i];
    }
    if (t < 50) bs[t] = bias[t];

    int row0 = blockIdx.x << 2;
    if (t < 64) {
        int r = t >> 4, k = t & 15;
        int row = row0 + r;
        hs[r][k] = (row < N) ? g_h1[b][row * 16 + k] : 0.f;
    } else if (t < 128) {
        int tt = t - 64;
        int r = tt >> 4, k = tt & 15;
        int row = row0 + r;
        as_[r][k] = (row < N) ? g_agg2[b][row * 16 + k] : 0.f;
    }
    __syncthreads();

    int o = t & 63;
    int r = t >> 6;
    int row = row0 + r;
    if (o < 50 && row < N) {
        float acc = bs[o];
#pragma unroll
        for (int k = 0; k < 16; k++) {
            acc = fmaf(hs[r][k], ws1[k * 50 + o], acc);
            acc = fmaf(as_[r][k], ws2[k * 50 + o], acc);
        }
        g_mol[row * 100 + col0 + o] = acc;
    }
}

// ---------------------------------------------------------------------------
// Kernel 5: MLP head. One thread per row; row (100 floats) in registers,
// all weights in smem (w_in transposed to [60][25] float4 for LDS.128
// uniform-broadcast reads).
// ---------------------------------------------------------------------------
__global__ __launch_bounds__(128)
void head_kernel(const float* __restrict__ action,
                 const float* __restrict__ w_in, const float* __restrict__ b_in,
                 const float* __restrict__ w_hid, const float* __restrict__ b_hid,
                 const float* __restrict__ w_out, const float* __restrict__ b_out,
                 float* __restrict__ out, int N) {
    __shared__ float4 wst[60 * 25];  // transposed w_in: [o][kk] -> 4 k-values
    __shared__ float wh[700];
    __shared__ float bi[60];
    __shared__ float bh[10];
    __shared__ float wo[10];
    __shared__ float bo;
    int t = threadIdx.x;
    for (int i = t; i < 1500; i += 128) {
        int o = i / 25, kk = i % 25;
        float4 v;
        v.x = w_in[(kk * 4 + 0) * 60 + o];
        v.y = w_in[(kk * 4 + 1) * 60 + o];
        v.z = w_in[(kk * 4 + 2) * 60 + o];
        v.w = w_in[(kk * 4 + 3) * 60 + o];
        wst[i] = v;
    }
    for (int i = t; i < 700; i += 128) wh[i] = w_hid[i];
    if (t < 60) bi[t] = b_in[t];
    if (t < 10) { bh[t] = b_hid[t]; wo[t] = w_out[t]; }
    if (t == 0) bo = b_out[0];
    __syncthreads();

    int row = blockIdx.x * 128 + t;
    if (row >= N) return;

    float4 xr[25];
    const float4* m4 = (const float4*)(g_mol + (size_t)row * 100);
#pragma unroll
    for (int i = 0; i < 25; i++) xr[i] = m4[i];

    float pol[10];
#pragma unroll
    for (int a = 0; a < 10; a++) pol[a] = bh[a];

    for (int o = 0; o < 60; o++) {
        float acc = bi[o];
        const float4* wc = wst + o * 25;
#pragma unroll
        for (int kk = 0; kk < 25; kk++) {
            float4 w4 = wc[kk];
            acc = fmaf(xr[kk].x, w4.x, acc);
            acc = fmaf(xr[kk].y, w4.y, acc);
            acc = fmaf(xr[kk].z, w4.z, acc);
            acc = fmaf(xr[kk].w, w4.w, acc);
        }
        float f = fmaxf(acc, 0.f);
#pragma unroll
        for (int a = 0; a < 10; a++) pol[a] = fmaf(f, wh[o * 10 + a], pol[a]);
    }

    const float* arow = action + (size_t)row * 10;
#pragma unroll
    for (int j = 0; j < 10; j++) {
        float av = arow[j];
#pragma unroll
        for (int a = 0; a < 10; a++) pol[a] = fmaf(av, wh[(60 + j) * 10 + a], pol[a]);
    }

    float res = bo;
#pragma unroll
    for (int a = 0; a < 10; a++) res = fmaf(fmaxf(pol[a], 0.f), wo[a], res);
    out[row] = res;
}

// ---------------------------------------------------------------------------
extern "C" void kernel_launch(void* const* d_in, const int* in_sizes, int n_in,
                              void* d_out, int out_size) {
    const float* px = (const float*)d_in[0];
    const int*   pe = (const int*)d_in[1];
    const float* lx = (const float*)d_in[2];
    const int*   le = (const int*)d_in[3];
    const float* action = (const float*)d_in[4];
    const float* wp1s = (const float*)d_in[5];
    const float* wp1n = (const float*)d_in[6];
    const float* bp1  = (const float*)d_in[7];
    const float* wp2s = (const float*)d_in[8];
    const float* wp2n = (const float*)d_in[9];
    const float* bp2  = (const float*)d_in[10];
    const float* wl1s = (const float*)d_in[11];
    const float* wl1n = (const float*)d_in[12];
    const float* bl1  = (const float*)d_in[13];
    const float* wl2s = (const float*)d_in[14];
    const float* wl2n = (const float*)d_in[15];
    const float* bl2  = (const float*)d_in[16];
    const float* w_in  = (const float*)d_in[17];
    const float* b_in  = (const float*)d_in[18];
    const float* w_hid = (const float*)d_in[19];
    const float* b_hid = (const float*)d_in[20];
    const float* w_out = (const float*)d_in[21];
    const float* b_out = (const float*)d_in[22];
    float* out = (float*)d_out;

    int N = in_sizes[0] / 128;
    int Es[2] = {in_sizes[1] / 2, in_sizes[3] / 2};
    const float* xs[2] = {px, lx};
    const int* es[2] = {pe, le};
    const float* w1s[2] = {wp1s, wl1s};
    const float* w1n[2] = {wp1n, wl1n};
    const float* b1[2]  = {bp1, bl1};
    const float* w2s[2] = {wp2s, wl2s};
    const float* w2n[2] = {wp2n, wl2n};
    const float* b2[2]  = {bp2, bl2};

    for (int b = 0; b < 2; b++) {
        int E = Es[b];
        proj_kernel<<<(N + 31) / 32, 256>>>(xs[b], w1s[b], w1n[b], b1[b], b, N);
        agg_kernel<<<(E * 4 + 255) / 256, 256>>>(es[b], es[b] + E, b, 0, E);
        relu_kernel<<<(N * 4 + 255) / 256, 256>>>(b, N * 4);
        agg_kernel<<<(E * 4 + 255) / 256, 256>>>(es[b], es[b] + E, b, 1, E);
        layer2_kernel<<<(N + 3) / 4, 256>>>(b, w2s[b], w2n[b], b2[b], 50 * b, N);
    }
    head_kernel<<<(N + 127) / 128, 128>>>(action, w_in, b_in, w_hid, b_hid,
                                          w_out, b_out, out, N);
}

// round 7
// speedup vs baseline: 1.0511x; 1.0040x over previous
#include <cuda_runtime.h>

#define NN 100000
#define EMAX 3400000

// ---------------------------------------------------------------------------
// Scratch (device globals — no allocation allowed)
// ---------------------------------------------------------------------------
__device__ __align__(16) float g_y[2][NN * 16];     // x @ w_nbr
__device__ __align__(16) float g_agg1[2][NN * 16];  // x@w_self+b, then += gather(y)
__device__ __align__(16) float g_agg2[2][NN * 16];  // gather(relu(agg1))
__device__ __align__(16) float g_mol[NN * 100];     // concat(p, l)
__device__ __align__(16) float4 g_wst[1500];        // transposed w_in [60][25] float4
__device__ __align__(16) int g_cnt[2][NN];          // per-node in-degree
__device__ __align__(16) int g_cur[2][NN];          // scatter cursor -> row end
__device__ __align__(16) int g_part[2][NN];         // row start (after fixup)
__device__ __align__(16) int g_top[2][128];         // block-sum exclusive scan
__device__ __align__(16) int g_csr[2][EMAX];        // src ids grouped by dst

// ---------------------------------------------------------------------------
// packed f32x2 helpers (sm_10x packed fp32 pipe — 2x FFMA throughput)
// ---------------------------------------------------------------------------
static __device__ __forceinline__ unsigned long long pk2(float x, float y) {
    unsigned long long r;
    asm("mov.b64 %0, {%1,%2};" : "=l"(r) : "f"(x), "f"(y));
    return r;
}
static __device__ __forceinline__ float2 upk2(unsigned long long v) {
    float2 r;
    asm("mov.b64 {%0,%1}, %2;" : "=f"(r.x), "=f"(r.y) : "l"(v));
    return r;
}
static __device__ __forceinline__ unsigned long long fma2(
    unsigned long long a, unsigned long long b, unsigned long long c) {
    unsigned long long d;
    asm("fma.rn.f32x2 %0, %1, %2, %3;" : "=l"(d) : "l"(a), "l"(b), "l"(c));
    return d;
}

// ---------------------------------------------------------------------------
// Prep: transpose w_in [100,60] -> g_wst[o][kk] float4 (k-major packed).
// One-time, so head blocks load it coalesced instead of 4.7M scattered reads.
// ---------------------------------------------------------------------------
__global__ void prep_head(const float* __restrict__ w_in) {
    int i = blockIdx.x * 128 + threadIdx.x;
    if (i < 1500) {
        int o = i / 25, kk = i % 25;
        float4 v;
        v.x = w_in[(kk * 4 + 0) * 60 + o];
        v.y = w_in[(kk * 4 + 1) * 60 + o];
        v.z = w_in[(kk * 4 + 2) * 60 + o];
        v.w = w_in[(kk * 4 + 3) * 60 + o];
        g_wst[i] = v;
    }
}

// ---------------------------------------------------------------------------
// Layer-1 projection (both branches via blockIdx.y):
//   y    = x @ w_nbr        [N,16]
//   agg1 = x @ w_self + b   [N,16]
// Also zeroes g_cnt for the CSR build.
// ---------------------------------------------------------------------------
__global__ void proj_kernel(const float* __restrict__ x0, const float* __restrict__ x1,
                            const float* __restrict__ ws0, const float* __restrict__ ws1,
                            const float* __restrict__ wn0, const float* __restrict__ wn1,
                            const float* __restrict__ bb0, const float* __restrict__ bb1,
                            int N) {
    int b = blockIdx.y;
    const float* x = b ? x1 : x0;
    const float* w_self = b ? ws1 : ws0;
    const float* w_nbr = b ? wn1 : wn0;
    const float* bias = b ? bb1 : bb0;

    __shared__ __align__(16) float xs[32][128];
    __shared__ __align__(16) float ws[128][32];  // cols 0-15: w_nbr, 16-31: w_self
    int t = threadIdx.x;
    int row0 = blockIdx.x << 5;

    if (t < 32) {
        int r = row0 + t;
        if (r < N) g_cnt[b][r] = 0;
    }
    for (int i = t; i < 2048; i += 256) {
        int k = i >> 4, o = i & 15;
        ws[k][o] = w_nbr[i];
        ws[k][o + 16] = w_self[i];
    }
    const float4* x4 = (const float4*)x;
    float4* xs4 = (float4*)xs;
    int base = row0 * 32;
    int lim = N * 32;
    for (int i = t; i < 1024; i += 256) {
        int g = base + i;
        xs4[i] = (g < lim) ? x4[g] : make_float4(0.f, 0.f, 0.f, 0.f);
    }
    __syncthreads();

    int og = (t & 7) << 2;
    int r = t >> 3;
    unsigned long long a0 = 0, a1 = 0;
#pragma unroll 16
    for (int k = 0; k < 128; k++) {
        float xv = xs[r][k];
        unsigned long long xv2 = pk2(xv, xv);
        ulonglong2 wv = *(const ulonglong2*)&ws[k][og];
        a0 = fma2(xv2, wv.x, a0);
        a1 = fma2(xv2, wv.y, a1);
    }
    float2 p0 = upk2(a0), p1 = upk2(a1);
    float4 acc = make_float4(p0.x, p0.y, p1.x, p1.y);

    int row = row0 + r;
    if (row < N) {
        if (og < 16) {
            *(float4*)(g_y[b] + row * 16 + og) = acc;
        } else {
            int o = og - 16;
            float4 bb = *(const float4*)(bias + o);
            acc.x += bb.x; acc.y += bb.y; acc.z += bb.z; acc.w += bb.w;
            *(float4*)(g_agg1[b] + row * 16 + o) = acc;
        }
    }
}

// ---------------------------------------------------------------------------
// CSR build step 1: in-degree histogram.
// ---------------------------------------------------------------------------
__global__ void count_kernel(const int* __restrict__ d0, const int* __restrict__ d1,
                             int E0, int E1) {
    int b = blockIdx.y;
    const int* dst = b ? d1 : d0;
    int E = b ? E1 : E0;
    int e = blockIdx.x * 256 + threadIdx.x;
    if (e < E) atomicAdd(&g_cnt[b][dst[e]], 1);
}

// ---------------------------------------------------------------------------
// CSR build step 2a: block-level exclusive scan (1024 elems / block of 256).
// ---------------------------------------------------------------------------
__global__ void scan1_kernel(int N) {
    int b = blockIdx.y;
    __shared__ int sh[256];
    int t = threadIdx.x;
    int base = blockIdx.x * 1024 + t * 4;
    int v0 = 0, v1 = 0, v2 = 0, v3 = 0;
    if (base + 3 < N) {
        int4 v = *(const int4*)&g_cnt[b][base];
        v0 = v.x; v1 = v.y; v2 = v.z; v3 = v.w;
    } else {
        if (base < N) v0 = g_cnt[b][base];
        if (base + 1 < N) v1 = g_cnt[b][base + 1];
        if (base + 2 < N) v2 = g_cnt[b][base + 2];
        if (base + 3 < N) v3 = g_cnt[b][base + 3];
    }
    int s = v0 + v1 + v2 + v3;
    sh[t] = s;
    __syncthreads();
    for (int off = 1; off < 256; off <<= 1) {
        int xx = (t >= off) ? sh[t - off] : 0;
        __syncthreads();
        sh[t] += xx;
        __syncthreads();
    }
    int excl = sh[t] - s;
    if (base < N) g_part[b][base] = excl;
    if (base + 1 < N) g_part[b][base + 1] = excl + v0;
    if (base + 2 < N) g_part[b][base + 2] = excl + v0 + v1;
    if (base + 3 < N) g_part[b][base + 3] = excl + v0 + v1 + v2;
    if (t == 255) g_top[b][blockIdx.x] = sh[255];
}

// ---------------------------------------------------------------------------
// CSR build step 2b: scan of block sums (nb <= 128). blockIdx.x = branch.
// ---------------------------------------------------------------------------
__global__ void scan2_kernel(int nb) {
    int b = blockIdx.x;
    int t = threadIdx.x;
    __shared__ int sh[128];
    int v = (t < nb) ? g_top[b][t] : 0;
    sh[t] = v;
    __syncthreads();
    for (int off = 1; off < 128; off <<= 1) {
        int xx = (t >= off) ? sh[t - off] : 0;
        __syncthreads();
        sh[t] += xx;
        __syncthreads();
    }
    if (t < nb) g_top[b][t] = sh[t] - v;
}

// ---------------------------------------------------------------------------
// CSR build step 2c: absolute row starts; cursor = row start.
// ---------------------------------------------------------------------------
__global__ void fixup_kernel(int N) {
    int b = blockIdx.y;
    int d = blockIdx.x * 256 + threadIdx.x;
    if (d < N) {
        int rs = g_part[b][d] + g_top[b][d >> 10];
        g_part[b][d] = rs;
        g_cur[b][d] = rs;
    }
}

// ---------------------------------------------------------------------------
// CSR build step 3: scatter src ids into dst-grouped slots.
// After this, g_cur[b][d] == row end.
// ---------------------------------------------------------------------------
__global__ void scatter_kernel(const int* __restrict__ s0, const int* __restrict__ d0,
                               const int* __restrict__ s1, const int* __restrict__ d1,
                               int E0, int E1) {
    int b = blockIdx.y;
    const int* src = b ? s1 : s0;
    const int* dst = b ? d1 : d0;
    int E = b ? E1 : E0;
    int e = blockIdx.x * 256 + threadIdx.x;
    if (e >= E) return;
    int d = dst[e];
    int slot = atomicAdd(&g_cur[b][d], 1);
    g_csr[b][slot] = src[e];
}

// ---------------------------------------------------------------------------
// Gather aggregation: one warp per node, 4 lanes x 16B per neighbor row.
// PASS 0: agg1 += sum y[src]           (agg1 holds self+bias)
// PASS 1: agg2  = sum relu(agg1[src])  (relu fused into the gather)
// ---------------------------------------------------------------------------
template <int PASS>
__global__ void gather_kernel(int N) {
    int b = blockIdx.y;
    int node = blockIdx.x * 8 + (threadIdx.x >> 5);
    if (node >= N) return;
    int lane = threadIdx.x & 31;
    int q4 = (lane & 3) << 2;
    int start = g_part[b][node];
    int end = g_cur[b][node];
    const int* __restrict__ csr = g_csr[b];
    const float* __restrict__ V = PASS ? g_agg1[b] : g_y[b];

    float4 acc = make_float4(0.f, 0.f, 0.f, 0.f);
    for (int k = start + (lane >> 2); k < end; k += 8) {
        int s = __ldg(csr + k);
        float4 v = *(const float4*)(V + s * 16 + q4);
        if (PASS) {
            acc.x += fmaxf(v.x, 0.f);
            acc.y += fmaxf(v.y, 0.f);
            acc.z += fmaxf(v.z, 0.f);
            acc.w += fmaxf(v.w, 0.f);
        } else {
            acc.x += v.x; acc.y += v.y; acc.z += v.z; acc.w += v.w;
        }
    }
#pragma unroll
    for (int off = 4; off < 32; off <<= 1) {
        acc.x += __shfl_xor_sync(0xffffffffu, acc.x, off);
        acc.y += __shfl_xor_sync(0xffffffffu, acc.y, off);
        acc.z += __shfl_xor_sync(0xffffffffu, acc.z, off);
        acc.w += __shfl_xor_sync(0xffffffffu, acc.w, off);
    }
    if (lane < 4) {
        float* dp = (PASS ? g_agg2[b] : g_agg1[b]) + node * 16 + q4;
        if (!PASS) {
            float4 c0 = *(const float4*)dp;
            acc.x += c0.x; acc.y += c0.y; acc.z += c0.z; acc.w += c0.w;
        }
        *(float4*)dp = acc;
    }
}

// ---------------------------------------------------------------------------
// Layer-2 conv:  mol[:, col0:col0+50] = relu(agg1) @ w_s + agg2 @ w_n + b
// h/agg pairs packed into f32x2; weights interleaved (w_s, w_n) per (k,o).
// ---------------------------------------------------------------------------
__global__ void layer2_kernel(const float* __restrict__ ws0, const float* __restrict__ ws1,
                              const float* __restrict__ wn0, const float* __restrict__ wn1,
                              const float* __restrict__ bb0, const float* __restrict__ bb1,
                              int N) {
    int b = blockIdx.y;
    const float* w_s = b ? ws1 : ws0;
    const float* w_n = b ? wn1 : wn0;
    const float* bias = b ? bb1 : bb0;
    int col0 = b * 50;

    __shared__ __align__(16) unsigned long long wsi[800];
    __shared__ __align__(16) unsigned long long ha[4][16];
    __shared__ float bs[52];
    int t = threadIdx.x;
    for (int i = t; i < 800; i += 256) wsi[i] = pk2(w_s[i], w_n[i]);
    if (t < 50) bs[t] = bias[t];

    int row0 = blockIdx.x << 2;
    if (t < 64) {
        int r = t >> 4, k = t & 15;
        int row = row0 + r;
        float h = 0.f, a = 0.f;
        if (row < N) {
            h = fmaxf(g_agg1[b][row * 16 + k], 0.f);
            a = g_agg2[b][row * 16 + k];
        }
        ha[r][k] = pk2(h, a);
    }
    __syncthreads();

    int o = t & 63, r = t >> 6;
    int row = row0 + r;
    if (o < 50 && row < N) {
        unsigned long long a0 = 0, a1 = 0;
#pragma unroll
        for (int k = 0; k < 16; k += 2) {
            a0 = fma2(ha[r][k], wsi[k * 50 + o], a0);
            a1 = fma2(ha[r][k + 1], wsi[(k + 1) * 50 + o], a1);
        }
        float2 p = upk2(a0), q = upk2(a1);
        g_mol[row * 100 + col0 + o] = bs[o] + ((p.x + p.y) + (q.x + q.y));
    }
}

// ---------------------------------------------------------------------------
// MLP head, one thread per row; inner GEMV in packed f32x2.
// ---------------------------------------------------------------------------
__global__ __launch_bounds__(128)
void head_kernel(const float* __restrict__ action,
                 const float* __restrict__ b_in, const float* __restrict__ w_hid,
                 const float* __restrict__ b_hid, const float* __restrict__ w_out,
                 const float* __restrict__ b_out, float* __restrict__ out, int N) {
    __shared__ __align__(16) float4 wst[1500];
    __shared__ __align__(16) float wh[700];
    __shared__ float bi[60];
    __shared__ __align__(16) float bh[12];
    __shared__ float wo[10];
    __shared__ float bo;
    int t = threadIdx.x;
    for (int i = t; i < 1500; i += 128) wst[i] = g_wst[i];
    for (int i = t; i < 700; i += 128) wh[i] = w_hid[i];
    if (t < 60) bi[t] = b_in[t];
    if (t < 10) { bh[t] = b_hid[t]; wo[t] = w_out[t]; }
    if (t == 0) bo = b_out[0];
    __syncthreads();

    int row = blockIdx.x * 128 + t;
    if (row >= N) return;

    ulonglong2 xr[25];
    const ulonglong2* m2 = (const ulonglong2*)(g_mol + (size_t)row * 100);
#pragma unroll
    for (int i = 0; i < 25; i++) xr[i] = m2[i];

    unsigned long long pol2[5];
    const unsigned long long* bh2 = (const unsigned long long*)bh;
#pragma unroll
    for (int a = 0; a < 5; a++) pol2[a] = bh2[a];

#pragma unroll 1
    for (int o = 0; o < 60; o++) {
        const ulonglong2* wr = (const ulonglong2*)(wst + o * 25);
        unsigned long long a0 = 0, a1 = 0;
#pragma unroll
        for (int kk = 0; kk < 25; kk++) {
            ulonglong2 wv = wr[kk];
            a0 = fma2(xr[kk].x, wv.x, a0);
            a1 = fma2(xr[kk].y, wv.y, a1);
        }
        float2 p = upk2(a0), q = upk2(a1);
        float f = fmaxf(bi[o] + ((p.x + p.y) + (q.x + q.y)), 0.f);
        unsigned long long f2 = pk2(f, f);
        const unsigned long long* whp = (const unsigned long long*)(wh + o * 10);
#pragma unroll
        for (int a = 0; a < 5; a++) pol2[a] = fma2(f2, whp[a], pol2[a]);
    }

    const unsigned long long* a2 = (const unsigned long long*)(action + (size_t)row * 10);
#pragma unroll
    for (int jj = 0; jj < 5; jj++) {
        float2 ap = upk2(a2[jj]);
        unsigned long long u = pk2(ap.x, ap.x);
        unsigned long long v = pk2(ap.y, ap.y);
        const unsigned long long* w1 = (const unsigned long long*)(wh + (60 + 2 * jj) * 10);
        const unsigned long long* w2p = (const unsigned long long*)(wh + (61 + 2 * jj) * 10);
#pragma unroll
        for (int a = 0; a < 5; a++) {
            pol2[a] = fma2(u, w1[a], pol2[a]);
            pol2[a] = fma2(v, w2p[a], pol2[a]);
        }
    }

    float res = bo;
#pragma unroll
    for (int a = 0; a < 5; a++) {
        float2 p = upk2(pol2[a]);
        res = fmaf(fmaxf(p.x, 0.f), wo[2 * a], res);
        res = fmaf(fmaxf(p.y, 0.f), wo[2 * a + 1], res);
    }
    out[row] = res;
}

// ---------------------------------------------------------------------------
extern "C" void kernel_launch(void* const* d_in, const int* in_sizes, int n_in,
                              void* d_out, int out_size) {
    const float* px = (const float*)d_in[0];
    const int*   pe = (const int*)d_in[1];
    const float* lx = (const float*)d_in[2];
    const int*   le = (const int*)d_in[3];
    const float* action = (const float*)d_in[4];
    const float* wp1s = (const float*)d_in[5];
    const float* wp1n = (const float*)d_in[6];
    const float* bp1  = (const float*)d_in[7];
    const float* wp2s = (const float*)d_in[8];
    const float* wp2n = (const float*)d_in[9];
    const float* bp2  = (const float*)d_in[10];
    const float* wl1s = (const float*)d_in[11];
    const float* wl1n = (const float*)d_in[12];
    const float* bl1  = (const float*)d_in[13];
    const float* wl2s = (const float*)d_in[14];
    const float* wl2n = (const float*)d_in[15];
    const float* bl2  = (const float*)d_in[16];
    const float* w_in  = (const float*)d_in[17];
    const float* b_in  = (const float*)d_in[18];
    const float* w_hid = (const float*)d_in[19];
    const float* b_hid = (const float*)d_in[20];
    const float* w_out = (const float*)d_in[21];
    const float* b_out = (const float*)d_in[22];
    float* out = (float*)d_out;

    int N = in_sizes[0] / 128;
    int E0 = in_sizes[1] / 2;
    int E1 = in_sizes[3] / 2;
    int Em = (E0 > E1) ? E0 : E1;
    int nb = (N + 1023) / 1024;

    prep_head<<<12, 128>>>(w_in);

    dim3 gp((N + 31) / 32, 2);
    proj_kernel<<<gp, 256>>>(px, lx, wp1s, wl1s, wp1n, wl1n, bp1, bl1, N);

    dim3 ge((Em + 255) / 256, 2);
    count_kernel<<<ge, 256>>>(pe + E0, le + E1, E0, E1);

    dim3 gs(nb, 2);
    scan1_kernel<<<gs, 256>>>(N);
    scan2_kernel<<<2, 128>>>(nb);

    dim3 gf((N + 255) / 256, 2);
    fixup_kernel<<<gf, 256>>>(N);

    scatter_kernel<<<ge, 256>>>(pe, pe + E0, le, le + E1, E0, E1);

    dim3 gg((N + 7) / 8, 2);
    gather_kernel<0><<<gg, 256>>>(N);
    gather_kernel<1><<<gg, 256>>>(N);

    dim3 gl((N + 3) / 4, 2);
    layer2_kernel<<<gl, 256>>>(wp2s, wl2s, wp2n, wl2n, bp2, bl2, N);

    head_kernel<<<(N + 127) / 128, 128>>>(action, b_in, w_hid, b_hid,
                                          w_out, b_out, out, N);
}

// round 8
// speedup vs baseline: 1.3094x; 1.2457x over previous
#include <cuda_runtime.h>
#include <cuda_fp16.h>

#define NN 100000
#define EMAX 3400000

// ---------------------------------------------------------------------------
// Scratch (device globals — no allocation allowed)
// ---------------------------------------------------------------------------
__device__ __align__(16) __half g_yh[2][NN * 16];   // x @ w_nbr (fp16 payload)
__device__ __align__(16) float g_a1i[2][NN * 16];   // x @ w_self + b (init)
__device__ __align__(16) float g_h1f[2][NN * 16];   // relu(agg1) fp32 (for tail)
__device__ __align__(16) __half g_h1h[2][NN * 16];  // relu(agg1) fp16 (for pass 1)
__device__ __align__(16) float g_agg2[2][NN * 16];  // segsum(relu(agg1))
__device__ __align__(16) float4 g_wst[1500];        // transposed w_in [60][25] f4
__device__ __align__(16) unsigned long long g_wsi2[2][800];  // (w2s,w2n) packed
__device__ __align__(16) int g_cnt[2][NN];
__device__ __align__(16) int g_cur[2][NN];   // scatter cursor -> row end
__device__ __align__(16) int g_part[2][NN];  // row start
__device__ __align__(16) int g_top[2][128];
__device__ __align__(16) int g_csr[2][EMAX];

// ---------------------------------------------------------------------------
// packed f32x2 helpers
// ---------------------------------------------------------------------------
static __device__ __forceinline__ unsigned long long pk2(float x, float y) {
    unsigned long long r;
    asm("mov.b64 %0, {%1,%2};" : "=l"(r) : "f"(x), "f"(y));
    return r;
}
static __device__ __forceinline__ float2 upk2(unsigned long long v) {
    float2 r;
    asm("mov.b64 {%0,%1}, %2;" : "=f"(r.x), "=f"(r.y) : "l"(v));
    return r;
}
static __device__ __forceinline__ unsigned long long fma2(
    unsigned long long a, unsigned long long b, unsigned long long c) {
    unsigned long long d;
    asm("fma.rn.f32x2 %0, %1, %2, %3;" : "=l"(d) : "l"(a), "l"(b), "l"(c));
    return d;
}

// ---------------------------------------------------------------------------
// Prep: pack/transpose small weights once.
//   g_wst : w_in [100,60] -> [o][kk] float4
//   g_wsi2: layer-2 (w_self, w_nbr) interleaved f32x2 per (k,o), both branches
// ---------------------------------------------------------------------------
__global__ void prep_kernel(const float* __restrict__ w_in,
                            const float* __restrict__ wp2s, const float* __restrict__ wp2n,
                            const float* __restrict__ wl2s, const float* __restrict__ wl2n) {
    int i = blockIdx.x * 256 + threadIdx.x;
    if (i < 1500) {
        int o = i / 25, kk = i % 25;
        float4 v;
        v.x = w_in[(kk * 4 + 0) * 60 + o];
        v.y = w_in[(kk * 4 + 1) * 60 + o];
        v.z = w_in[(kk * 4 + 2) * 60 + o];
        v.w = w_in[(kk * 4 + 3) * 60 + o];
        g_wst[i] = v;
    } else if (i < 2300) {
        int j = i - 1500;
        g_wsi2[0][j] = pk2(wp2s[j], wp2n[j]);
    } else if (i < 3100) {
        int j = i - 2300;
        g_wsi2[1][j] = pk2(wl2s[j], wl2n[j]);
    }
}

// ---------------------------------------------------------------------------
// Layer-1 projection, register-blocked. Block 256 threads computes a
// 128-row x 32-out tile; thread = 2 rows x 8 outs (8 fma2 per k).
//   y    = x @ w_nbr  (outs 0..15, written fp16)
//   agg1 = x @ w_self + b (outs 16..31, written fp32 as the gather init)
// Also zeroes g_cnt for this tile's rows.
// ---------------------------------------------------------------------------
__global__ void proj_kernel(const float* __restrict__ x0, const float* __restrict__ x1,
                            const float* __restrict__ ws0, const float* __restrict__ ws1,
                            const float* __restrict__ wn0, const float* __restrict__ wn1,
                            const float* __restrict__ bb0, const float* __restrict__ bb1,
                            int N) {
    extern __shared__ float sm[];
    float* xs = sm;             // [128][129]
    float* ws = sm + 128 * 129; // [128][32]
    int b = blockIdx.y;
    const float* x = b ? x1 : x0;
    const float* w_self = b ? ws1 : ws0;
    const float* w_nbr = b ? wn1 : wn0;
    const float* bias = b ? bb1 : bb0;
    int t = threadIdx.x;
    int row0 = blockIdx.x << 7;

    if (t < 128) {
        int r = row0 + t;
        if (r < N) g_cnt[b][r] = 0;
    }
    for (int i = t; i < 2048; i += 256) {
        int k = i >> 4, o = i & 15;
        ws[k * 32 + o] = w_nbr[i];
        ws[k * 32 + o + 16] = w_self[i];
    }
    const float4* x4 = (const float4*)x;
    for (int i = t; i < 4096; i += 256) {
        int r = i >> 5, c4 = i & 31;
        int row = row0 + r;
        float4 v = (row < N) ? x4[row * 32 + c4] : make_float4(0.f, 0.f, 0.f, 0.f);
        float* p = xs + r * 129 + c4 * 4;
        p[0] = v.x; p[1] = v.y; p[2] = v.z; p[3] = v.w;
    }
    __syncthreads();

    int og = t & 3;   // outs og*8 .. og*8+7
    int rg = t >> 2;  // rows 2rg, 2rg+1
    const float* xr0 = xs + (2 * rg) * 129;
    const float* xr1 = xs + (2 * rg + 1) * 129;
    const float* wp = ws + og * 8;

    unsigned long long a0 = 0, a1 = 0, a2 = 0, a3 = 0;
    unsigned long long a4 = 0, a5 = 0, a6 = 0, a7 = 0;
#pragma unroll 8
    for (int k = 0; k < 128; k++) {
        unsigned long long X0 = pk2(xr0[k], xr0[k]);
        unsigned long long X1 = pk2(xr1[k], xr1[k]);
        ulonglong2 wA = *(const ulonglong2*)(wp + k * 32);
        ulonglong2 wB = *(const ulonglong2*)(wp + k * 32 + 4);
        a0 = fma2(X0, wA.x, a0); a1 = fma2(X0, wA.y, a1);
        a2 = fma2(X0, wB.x, a2); a3 = fma2(X0, wB.y, a3);
        a4 = fma2(X1, wA.x, a4); a5 = fma2(X1, wA.y, a5);
        a6 = fma2(X1, wB.x, a6); a7 = fma2(X1, wB.y, a7);
    }

    int r0 = row0 + 2 * rg;
    int r1 = r0 + 1;
    if (og < 2) {  // y (neighbor proj) -> fp16
        int oy = og * 8;
#define EMIT_Y(ROW, A0, A1, A2, A3)                                          \
        if ((ROW) < N) {                                                     \
            float2 p0 = upk2(A0), p1 = upk2(A1), p2 = upk2(A2), p3 = upk2(A3);\
            __half2 h0 = __floats2half2_rn(p0.x, p0.y);                      \
            __half2 h1 = __floats2half2_rn(p1.x, p1.y);                      \
            __half2 h2 = __floats2half2_rn(p2.x, p2.y);                      \
            __half2 h3 = __floats2half2_rn(p3.x, p3.y);                      \
            uint4 hv;                                                        \
            hv.x = *(unsigned*)&h0; hv.y = *(unsigned*)&h1;                  \
            hv.z = *(unsigned*)&h2; hv.w = *(unsigned*)&h3;                  \
            *(uint4*)(g_yh[b] + (ROW) * 16 + oy) = hv;                       \
        }
        EMIT_Y(r0, a0, a1, a2, a3)
        EMIT_Y(r1, a4, a5, a6, a7)
#undef EMIT_Y
    } else {  // agg1 init = self + bias -> fp32
        int oa = og * 8 - 16;
        float4 b0 = *(const float4*)(bias + oa);
        float4 b1 = *(const float4*)(bias + oa + 4);
#define EMIT_A(ROW, A0, A1, A2, A3)                                          \
        if ((ROW) < N) {                                                     \
            float2 p0 = upk2(A0), p1 = upk2(A1), p2 = upk2(A2), p3 = upk2(A3);\
            float4 v0 = make_float4(p0.x + b0.x, p0.y + b0.y,                \
                                    p1.x + b0.z, p1.y + b0.w);               \
            float4 v1 = make_float4(p2.x + b1.x, p2.y + b1.y,                \
                                    p3.x + b1.z, p3.y + b1.w);               \
            *(float4*)(g_a1i[b] + (ROW) * 16 + oa) = v0;                     \
            *(float4*)(g_a1i[b] + (ROW) * 16 + oa + 4) = v1;                 \
        }
        EMIT_A(r0, a0, a1, a2, a3)
        EMIT_A(r1, a4, a5, a6, a7)
#undef EMIT_A
    }
}

// ---------------------------------------------------------------------------
// CSR build: count -> scan -> fixup -> scatter
// ---------------------------------------------------------------------------
__global__ void count_kernel(const int* __restrict__ d0, const int* __restrict__ d1,
                             int E0, int E1) {
    int b = blockIdx.y;
    const int* dst = b ? d1 : d0;
    int E = b ? E1 : E0;
    int e = blockIdx.x * 256 + threadIdx.x;
    if (e < E) atomicAdd(&g_cnt[b][dst[e]], 1);
}

__global__ void scan1_kernel(int N) {
    int b = blockIdx.y;
    __shared__ int sh[256];
    int t = threadIdx.x;
    int base = blockIdx.x * 1024 + t * 4;
    int v0 = 0, v1 = 0, v2 = 0, v3 = 0;
    if (base + 3 < N) {
        int4 v = *(const int4*)&g_cnt[b][base];
        v0 = v.x; v1 = v.y; v2 = v.z; v3 = v.w;
    } else {
        if (base < N) v0 = g_cnt[b][base];
        if (base + 1 < N) v1 = g_cnt[b][base + 1];
        if (base + 2 < N) v2 = g_cnt[b][base + 2];
    }
    int s = v0 + v1 + v2 + v3;
    sh[t] = s;
    __syncthreads();
    for (int off = 1; off < 256; off <<= 1) {
        int xx = (t >= off) ? sh[t - off] : 0;
        __syncthreads();
        sh[t] += xx;
        __syncthreads();
    }
    int excl = sh[t] - s;
    if (base < N) g_part[b][base] = excl;
    if (base + 1 < N) g_part[b][base + 1] = excl + v0;
    if (base + 2 < N) g_part[b][base + 2] = excl + v0 + v1;
    if (base + 3 < N) g_part[b][base + 3] = excl + v0 + v1 + v2;
    if (t == 255) g_top[b][blockIdx.x] = sh[255];
}

__global__ void scan2_kernel(int nb) {
    int b = blockIdx.x;
    int t = threadIdx.x;
    __shared__ int sh[128];
    int v = (t < nb) ? g_top[b][t] : 0;
    sh[t] = v;
    __syncthreads();
    for (int off = 1; off < 128; off <<= 1) {
        int xx = (t >= off) ? sh[t - off] : 0;
        __syncthreads();
        sh[t] += xx;
        __syncthreads();
    }
    if (t < nb) g_top[b][t] = sh[t] - v;
}

__global__ void fixup_kernel(int N) {
    int b = blockIdx.y;
    int d = blockIdx.x * 256 + threadIdx.x;
    if (d < N) {
        int rs = g_part[b][d] + g_top[b][d >> 10];
        g_part[b][d] = rs;
        g_cur[b][d] = rs;
    }
}

__global__ void scatter_kernel(const int* __restrict__ s0, const int* __restrict__ d0,
                               const int* __restrict__ s1, const int* __restrict__ d1,
                               int E0, int E1) {
    int b = blockIdx.y;
    const int* src = b ? s1 : s0;
    const int* dst = b ? d1 : d0;
    int E = b ? E1 : E0;
    int e = blockIdx.x * 256 + threadIdx.x;
    if (e >= E) return;
    int d = dst[e];
    int slot = atomicAdd(&g_cur[b][d], 1);
    g_csr[b][slot] = src[e];
}

// ---------------------------------------------------------------------------
// Gather aggregation over fp16 payload. 2 lanes per node (each 16B half-row),
// fp32 register accumulation, serial over the node's CSR row.
// PASS 0: agg1 = a1i + sum y[nbr];  h1f = relu(agg1);  h1h = fp16(h1f)
// PASS 1: agg2 = sum h1h[nbr]   (already relu'd)
// ---------------------------------------------------------------------------
template <int PASS>
__global__ void gather_kernel(int N) {
    int b = blockIdx.y;
    int t = threadIdx.x;
    int node = blockIdx.x * 128 + (t >> 1);
    if (node >= N) return;
    int h = t & 1;
    int start = g_part[b][node];
    int end = g_cur[b][node];
    const int* __restrict__ csr = g_csr[b];
    const __half* __restrict__ Y = PASS ? g_h1h[b] : g_yh[b];

    float2 c0 = make_float2(0.f, 0.f), c1 = c0, c2 = c0, c3 = c0;
    for (int k = start; k < end; k++) {
        int s = __ldg(csr + k);
        uint4 raw = *(const uint4*)(Y + ((size_t)s << 4) + (h << 3));
        float2 f0 = __half22float2(*(const __half2*)&raw.x);
        float2 f1 = __half22float2(*(const __half2*)&raw.y);
        float2 f2 = __half22float2(*(const __half2*)&raw.z);
        float2 f3 = __half22float2(*(const __half2*)&raw.w);
        c0.x += f0.x; c0.y += f0.y;
        c1.x += f1.x; c1.y += f1.y;
        c2.x += f2.x; c2.y += f2.y;
        c3.x += f3.x; c3.y += f3.y;
    }

    size_t off = (size_t)node * 16 + (h << 3);
    if (PASS) {
        *(float4*)(g_agg2[b] + off) = make_float4(c0.x, c0.y, c1.x, c1.y);
        *(float4*)(g_agg2[b] + off + 4) = make_float4(c2.x, c2.y, c3.x, c3.y);
    } else {
        const float4* ip = (const float4*)(g_a1i[b] + off);
        float4 i0 = ip[0], i1 = ip[1];
        float4 v0 = make_float4(fmaxf(c0.x + i0.x, 0.f), fmaxf(c0.y + i0.y, 0.f),
                                fmaxf(c1.x + i0.z, 0.f), fmaxf(c1.y + i0.w, 0.f));
        float4 v1 = make_float4(fmaxf(c2.x + i1.x, 0.f), fmaxf(c2.y + i1.y, 0.f),
                                fmaxf(c3.x + i1.z, 0.f), fmaxf(c3.y + i1.w, 0.f));
        *(float4*)(g_h1f[b] + off) = v0;
        *(float4*)(g_h1f[b] + off + 4) = v1;
        __half2 q0 = __floats2half2_rn(v0.x, v0.y);
        __half2 q1 = __floats2half2_rn(v0.z, v0.w);
        __half2 q2 = __floats2half2_rn(v1.x, v1.y);
        __half2 q3 = __floats2half2_rn(v1.z, v1.w);
        uint4 hv;
        hv.x = *(unsigned*)&q0; hv.y = *(unsigned*)&q1;
        hv.z = *(unsigned*)&q2; hv.w = *(unsigned*)&q3;
        *(uint4*)(g_h1h[b] + off) = hv;
    }
}

// ---------------------------------------------------------------------------
// Fused tail: layer-2 convs (both branches) + MLP head, mol in registers.
// One thread per row.
// ---------------------------------------------------------------------------
__global__ __launch_bounds__(128)
void tail_kernel(const float* __restrict__ action,
                 const float* __restrict__ bp2, const float* __restrict__ bl2,
                 const float* __restrict__ b_in, const float* __restrict__ w_hid,
                 const float* __restrict__ b_hid, const float* __restrict__ w_out,
                 const float* __restrict__ b_out, float* __restrict__ out, int N) {
    __shared__ __align__(16) unsigned long long wsi[2][800];
    __shared__ __align__(16) float4 wst[1500];
    __shared__ __align__(16) float wh[700];
    __shared__ float bi[60];
    __shared__ float bs2[2][50];
    __shared__ __align__(16) float bh[12];
    __shared__ float wo[10];
    __shared__ float bo;
    int t = threadIdx.x;
    for (int i = t; i < 800; i += 128) {
        wsi[0][i] = g_wsi2[0][i];
        wsi[1][i] = g_wsi2[1][i];
    }
    for (int i = t; i < 1500; i += 128) wst[i] = g_wst[i];
    for (int i = t; i < 700; i += 128) wh[i] = w_hid[i];
    if (t < 60) bi[t] = b_in[t];
    if (t < 50) { bs2[0][t] = bp2[t]; bs2[1][t] = bl2[t]; }
    if (t < 10) { bh[t] = b_hid[t]; wo[t] = w_out[t]; }
    if (t == 0) bo = b_out[0];
    __syncthreads();

    int row = blockIdx.x * 128 + t;
    if (row >= N) return;

    unsigned long long molp[50];
#pragma unroll
    for (int b = 0; b < 2; b++) {
        unsigned long long ha[16];
        const float4* hp = (const float4*)(g_h1f[b] + (size_t)row * 16);
        const float4* ap = (const float4*)(g_agg2[b] + (size_t)row * 16);
#pragma unroll
        for (int q = 0; q < 4; q++) {
            float4 hv = hp[q], av = ap[q];
            ha[q * 4 + 0] = pk2(hv.x, av.x);
            ha[q * 4 + 1] = pk2(hv.y, av.y);
            ha[q * 4 + 2] = pk2(hv.z, av.z);
            ha[q * 4 + 3] = pk2(hv.w, av.w);
        }
        float prev = 0.f;
#pragma unroll 2
        for (int o = 0; o < 50; o++) {
            unsigned long long a0 = 0, a1 = 0;
#pragma unroll
            for (int k = 0; k < 16; k += 2) {
                a0 = fma2(ha[k], wsi[b][k * 50 + o], a0);
                a1 = fma2(ha[k + 1], wsi[b][(k + 1) * 50 + o], a1);
            }
            float2 p = upk2(a0), q = upk2(a1);
            float m = bs2[b][o] + ((p.x + p.y) + (q.x + q.y));
            if (o & 1) molp[(b * 50 + o) >> 1] = pk2(prev, m);
            else prev = m;
        }
    }

    unsigned long long pol2[5];
    const unsigned long long* bh2 = (const unsigned long long*)bh;
#pragma unroll
    for (int a = 0; a < 5; a++) pol2[a] = bh2[a];

#pragma unroll 1
    for (int o = 0; o < 60; o++) {
        const ulonglong2* wr = (const ulonglong2*)(wst + o * 25);
        unsigned long long a0 = 0, a1 = 0;
#pragma unroll
        for (int kk = 0; kk < 25; kk++) {
            ulonglong2 wv = wr[kk];
            a0 = fma2(molp[2 * kk], wv.x, a0);
            a1 = fma2(molp[2 * kk + 1], wv.y, a1);
        }
        float2 p = upk2(a0), q = upk2(a1);
        float f = fmaxf(bi[o] + ((p.x + p.y) + (q.x + q.y)), 0.f);
        unsigned long long f2 = pk2(f, f);
        const unsigned long long* whp = (const unsigned long long*)(wh + o * 10);
#pragma unroll
        for (int a = 0; a < 5; a++) pol2[a] = fma2(f2, whp[a], pol2[a]);
    }

    const unsigned long long* a2 = (const unsigned long long*)(action + (size_t)row * 10);
#pragma unroll
    for (int jj = 0; jj < 5; jj++) {
        float2 ap = upk2(a2[jj]);
        unsigned long long u = pk2(ap.x, ap.x);
        unsigned long long v = pk2(ap.y, ap.y);
        const unsigned long long* w1 = (const unsigned long long*)(wh + (60 + 2 * jj) * 10);
        const unsigned long long* w2p = (const unsigned long long*)(wh + (61 + 2 * jj) * 10);
#pragma unroll
        for (int a = 0; a < 5; a++) {
            pol2[a] = fma2(u, w1[a], pol2[a]);
            pol2[a] = fma2(v, w2p[a], pol2[a]);
        }
    }

    float res = bo;
#pragma unroll
    for (int a = 0; a < 5; a++) {
        float2 p = upk2(pol2[a]);
        res = fmaf(fmaxf(p.x, 0.f), wo[2 * a], res);
        res = fmaf(fmaxf(p.y, 0.f), wo[2 * a + 1], res);
    }
    out[row] = res;
}

// ---------------------------------------------------------------------------
extern "C" void kernel_launch(void* const* d_in, const int* in_sizes, int n_in,
                              void* d_out, int out_size) {
    const float* px = (const float*)d_in[0];
    const int*   pe = (const int*)d_in[1];
    const float* lx = (const float*)d_in[2];
    const int*   le = (const int*)d_in[3];
    const float* action = (const float*)d_in[4];
    const float* wp1s = (const float*)d_in[5];
    const float* wp1n = (const float*)d_in[6];
    const float* bp1  = (const float*)d_in[7];
    const float* wp2s = (const float*)d_in[8];
    const float* wp2n = (const float*)d_in[9];
    const float* bp2  = (const float*)d_in[10];
    const float* wl1s = (const float*)d_in[11];
    const float* wl1n = (const float*)d_in[12];
    const float* bl1  = (const float*)d_in[13];
    const float* wl2s = (const float*)d_in[14];
    const float* wl2n = (const float*)d_in[15];
    const float* bl2  = (const float*)d_in[16];
    const float* w_in  = (const float*)d_in[17];
    const float* b_in  = (const float*)d_in[18];
    const float* w_hid = (const float*)d_in[19];
    const float* b_hid = (const float*)d_in[20];
    const float* w_out = (const float*)d_in[21];
    const float* b_out = (const float*)d_in[22];
    float* out = (float*)d_out;

    int N = in_sizes[0] / 128;
    int E0 = in_sizes[1] / 2;
    int E1 = in_sizes[3] / 2;
    int Em = (E0 > E1) ? E0 : E1;
    int nb = (N + 1023) / 1024;

    prep_kernel<<<13, 256>>>(w_in, wp2s, wp2n, wl2s, wl2n);

    const int proj_smem = (128 * 129 + 128 * 32) * (int)sizeof(float);
    cudaFuncSetAttribute(proj_kernel, cudaFuncAttributeMaxDynamicSharedMemorySize,
                         proj_smem);
    dim3 gp((N + 127) / 128, 2);
    proj_kernel<<<gp, 256, proj_smem>>>(px, lx, wp1s, wl1s, wp1n, wl1n, bp1, bl1, N);

    dim3 ge((Em + 255) / 256, 2);
    count_kernel<<<ge, 256>>>(pe + E0, le + E1, E0, E1);

    dim3 gs(nb, 2);
    scan1_kernel<<<gs, 256>>>(N);
    scan2_kernel<<<2, 128>>>(nb);

    dim3 gf((N + 255) / 256, 2);
    fixup_kernel<<<gf, 256>>>(N);

    scatter_kernel<<<ge, 256>>>(pe, pe + E0, le, le + E1, E0, E1);

    dim3 gg((N + 127) / 128, 2);
    gather_kernel<0><<<gg, 256>>>(N);
    gather_kernel<1><<<gg, 256>>>(N);

    tail_kernel<<<(N + 127) / 128, 128>>>(action, bp2, bl2, b_in, w_hid, b_hid,
                                          w_out, b_out, out, N);
}

// round 9
// speedup vs baseline: 1.3799x; 1.0538x over previous
#include <cuda_runtime.h>
#include <cuda_fp16.h>

#define NN 100000
#define EMAX 3400000

// ---------------------------------------------------------------------------
// Scratch (device globals — no allocation allowed)
// ---------------------------------------------------------------------------
__device__ __align__(16) __half g_yh[2][NN * 16];   // x @ w_nbr (fp16 payload)
__device__ __align__(16) float g_a1i[2][NN * 16];   // x @ w_self + b (init)
__device__ __align__(16) float g_h1f[2][NN * 16];   // relu(agg1) fp32 (for tail)
__device__ __align__(16) __half g_h1h[2][NN * 16];  // relu(agg1) fp16 (for pass 1)
__device__ __align__(16) float g_agg2[2][NN * 16];  // segsum(relu(agg1))
__device__ __align__(16) float4 g_wst[1500];        // transposed w_in [60][25] f4
__device__ __align__(16) unsigned long long g_wsi2[2][800];  // (w2s,w2n) packed
__device__ __align__(16) int g_cnt[2][NN];
__device__ __align__(16) int g_cur[2][NN];   // scatter cursor -> row end
__device__ __align__(16) int g_part[2][NN];  // row start
__device__ __align__(16) int g_top[2][128];
__device__ __align__(16) int g_csr[2][EMAX];

// ---------------------------------------------------------------------------
// packed f32x2 helpers
// ---------------------------------------------------------------------------
static __device__ __forceinline__ unsigned long long pk2(float x, float y) {
    unsigned long long r;
    asm("mov.b64 %0, {%1,%2};" : "=l"(r) : "f"(x), "f"(y));
    return r;
}
static __device__ __forceinline__ float2 upk2(unsigned long long v) {
    float2 r;
    asm("mov.b64 {%0,%1}, %2;" : "=f"(r.x), "=f"(r.y) : "l"(v));
    return r;
}
static __device__ __forceinline__ unsigned long long fma2(
    unsigned long long a, unsigned long long b, unsigned long long c) {
    unsigned long long d;
    asm("fma.rn.f32x2 %0, %1, %2, %3;" : "=l"(d) : "l"(a), "l"(b), "l"(c));
    return d;
}

// ---------------------------------------------------------------------------
// Prep (CSR stream): zero in-degree tables + pack/transpose small weights.
// ---------------------------------------------------------------------------
__global__ void prep_kernel(const float* __restrict__ w_in,
                            const float* __restrict__ wp2s, const float* __restrict__ wp2n,
                            const float* __restrict__ wl2s, const float* __restrict__ wl2n) {
    int i = blockIdx.x * 256 + threadIdx.x;
    if (i < (2 * NN) / 4) ((int4*)g_cnt)[i] = make_int4(0, 0, 0, 0);
    if (i < 1500) {
        int o = i / 25, kk = i % 25;
        float4 v;
        v.x = w_in[(kk * 4 + 0) * 60 + o];
        v.y = w_in[(kk * 4 + 1) * 60 + o];
        v.z = w_in[(kk * 4 + 2) * 60 + o];
        v.w = w_in[(kk * 4 + 3) * 60 + o];
        g_wst[i] = v;
    } else if (i < 2300) {
        int j = i - 1500;
        g_wsi2[0][j] = pk2(wp2s[j], wp2n[j]);
    } else if (i < 3100) {
        int j = i - 2300;
        g_wsi2[1][j] = pk2(wl2s[j], wl2n[j]);
    }
}

// ---------------------------------------------------------------------------
// Layer-1 projection, register-blocked. Block 256 threads computes a
// 128-row x 32-out tile; thread = 2 rows x 8 outs (8 fma2 per k).
//   y    = x @ w_nbr  (outs 0..15, written fp16)
//   agg1 = x @ w_self + b (outs 16..31, written fp32 as the gather init)
// ---------------------------------------------------------------------------
__global__ void proj_kernel(const float* __restrict__ x0, const float* __restrict__ x1,
                            const float* __restrict__ ws0, const float* __restrict__ ws1,
                            const float* __restrict__ wn0, const float* __restrict__ wn1,
                            const float* __restrict__ bb0, const float* __restrict__ bb1,
                            int N) {
    extern __shared__ float sm[];
    float* xs = sm;             // [128][129]
    float* ws = sm + 128 * 129; // [128][32]
    int b = blockIdx.y;
    const float* x = b ? x1 : x0;
    const float* w_self = b ? ws1 : ws0;
    const float* w_nbr = b ? wn1 : wn0;
    const float* bias = b ? bb1 : bb0;
    int t = threadIdx.x;
    int row0 = blockIdx.x << 7;

    for (int i = t; i < 2048; i += 256) {
        int k = i >> 4, o = i & 15;
        ws[k * 32 + o] = w_nbr[i];
        ws[k * 32 + o + 16] = w_self[i];
    }
    const float4* x4 = (const float4*)x;
    for (int i = t; i < 4096; i += 256) {
        int r = i >> 5, c4 = i & 31;
        int row = row0 + r;
        float4 v = (row < N) ? x4[row * 32 + c4] : make_float4(0.f, 0.f, 0.f, 0.f);
        float* p = xs + r * 129 + c4 * 4;
        p[0] = v.x; p[1] = v.y; p[2] = v.z; p[3] = v.w;
    }
    __syncthreads();

    int og = t & 3;   // outs og*8 .. og*8+7
    int rg = t >> 2;  // rows 2rg, 2rg+1
    const float* xr0 = xs + (2 * rg) * 129;
    const float* xr1 = xs + (2 * rg + 1) * 129;
    const float* wp = ws + og * 8;

    unsigned long long a0 = 0, a1 = 0, a2 = 0, a3 = 0;
    unsigned long long a4 = 0, a5 = 0, a6 = 0, a7 = 0;
#pragma unroll 8
    for (int k = 0; k < 128; k++) {
        unsigned long long X0 = pk2(xr0[k], xr0[k]);
        unsigned long long X1 = pk2(xr1[k], xr1[k]);
        ulonglong2 wA = *(const ulonglong2*)(wp + k * 32);
        ulonglong2 wB = *(const ulonglong2*)(wp + k * 32 + 4);
        a0 = fma2(X0, wA.x, a0); a1 = fma2(X0, wA.y, a1);
        a2 = fma2(X0, wB.x, a2); a3 = fma2(X0, wB.y, a3);
        a4 = fma2(X1, wA.x, a4); a5 = fma2(X1, wA.y, a5);
        a6 = fma2(X1, wB.x, a6); a7 = fma2(X1, wB.y, a7);
    }

    int r0 = row0 + 2 * rg;
    int r1 = r0 + 1;
    if (og < 2) {  // y (neighbor proj) -> fp16
        int oy = og * 8;
#define EMIT_Y(ROW, A0, A1, A2, A3)                                          \
        if ((ROW) < N) {                                                     \
            float2 p0 = upk2(A0), p1 = upk2(A1), p2 = upk2(A2), p3 = upk2(A3);\
            __half2 h0 = __floats2half2_rn(p0.x, p0.y);                      \
            __half2 h1 = __floats2half2_rn(p1.x, p1.y);                      \
            __half2 h2 = __floats2half2_rn(p2.x, p2.y);                      \
            __half2 h3 = __floats2half2_rn(p3.x, p3.y);                      \
            uint4 hv;                                                        \
            hv.x = *(unsigned*)&h0; hv.y = *(unsigned*)&h1;                  \
            hv.z = *(unsigned*)&h2; hv.w = *(unsigned*)&h3;                  \
            *(uint4*)(g_yh[b] + (ROW) * 16 + oy) = hv;                       \
        }
        EMIT_Y(r0, a0, a1, a2, a3)
        EMIT_Y(r1, a4, a5, a6, a7)
#undef EMIT_Y
    } else {  // agg1 init = self + bias -> fp32
        int oa = og * 8 - 16;
        float4 b0 = *(const float4*)(bias + oa);
        float4 b1 = *(const float4*)(bias + oa + 4);
#define EMIT_A(ROW, A0, A1, A2, A3)                                          \
        if ((ROW) < N) {                                                     \
            float2 p0 = upk2(A0), p1 = upk2(A1), p2 = upk2(A2), p3 = upk2(A3);\
            float4 v0 = make_float4(p0.x + b0.x, p0.y + b0.y,                \
                                    p1.x + b0.z, p1.y + b0.w);               \
            float4 v1 = make_float4(p2.x + b1.x, p2.y + b1.y,                \
                                    p3.x + b1.z, p3.y + b1.w);               \
            *(float4*)(g_a1i[b] + (ROW) * 16 + oa) = v0;                     \
            *(float4*)(g_a1i[b] + (ROW) * 16 + oa + 4) = v1;                 \
        }
        EMIT_A(r0, a0, a1, a2, a3)
        EMIT_A(r1, a4, a5, a6, a7)
#undef EMIT_A
    }
}

// ---------------------------------------------------------------------------
// CSR build: count -> scan -> fixup -> scatter
// ---------------------------------------------------------------------------
__global__ void count_kernel(const int* __restrict__ d0, const int* __restrict__ d1,
                             int E0, int E1) {
    int b = blockIdx.y;
    const int* dst = b ? d1 : d0;
    int E = b ? E1 : E0;
    int e = blockIdx.x * 256 + threadIdx.x;
    if (e < E) atomicAdd(&g_cnt[b][dst[e]], 1);
}

__global__ void scan1_kernel(int N) {
    int b = blockIdx.y;
    __shared__ int sh[256];
    int t = threadIdx.x;
    int base = blockIdx.x * 1024 + t * 4;
    int v0 = 0, v1 = 0, v2 = 0, v3 = 0;
    if (base + 3 < N) {
        int4 v = *(const int4*)&g_cnt[b][base];
        v0 = v.x; v1 = v.y; v2 = v.z; v3 = v.w;
    } else {
        if (base < N) v0 = g_cnt[b][base];
        if (base + 1 < N) v1 = g_cnt[b][base + 1];
        if (base + 2 < N) v2 = g_cnt[b][base + 2];
    }
    int s = v0 + v1 + v2 + v3;
    sh[t] = s;
    __syncthreads();
    for (int off = 1; off < 256; off <<= 1) {
        int xx = (t >= off) ? sh[t - off] : 0;
        __syncthreads();
        sh[t] += xx;
        __syncthreads();
    }
    int excl = sh[t] - s;
    if (base < N) g_part[b][base] = excl;
    if (base + 1 < N) g_part[b][base + 1] = excl + v0;
    if (base + 2 < N) g_part[b][base + 2] = excl + v0 + v1;
    if (base + 3 < N) g_part[b][base + 3] = excl + v0 + v1 + v2;
    if (t == 255) g_top[b][blockIdx.x] = sh[255];
}

__global__ void scan2_kernel(int nb) {
    int b = blockIdx.x;
    int t = threadIdx.x;
    __shared__ int sh[128];
    int v = (t < nb) ? g_top[b][t] : 0;
    sh[t] = v;
    __syncthreads();
    for (int off = 1; off < 128; off <<= 1) {
        int xx = (t >= off) ? sh[t - off] : 0;
        __syncthreads();
        sh[t] += xx;
        __syncthreads();
    }
    if (t < nb) g_top[b][t] = sh[t] - v;
}

__global__ void fixup_kernel(int N) {
    int b = blockIdx.y;
    int d = blockIdx.x * 256 + threadIdx.x;
    if (d < N) {
        int rs = g_part[b][d] + g_top[b][d >> 10];
        g_part[b][d] = rs;
        g_cur[b][d] = rs;
    }
}

__global__ void scatter_kernel(const int* __restrict__ s0, const int* __restrict__ d0,
                               const int* __restrict__ s1, const int* __restrict__ d1,
                               int E0, int E1) {
    int b = blockIdx.y;
    const int* src = b ? s1 : s0;
    const int* dst = b ? d1 : d0;
    int E = b ? E1 : E0;
    int e = blockIdx.x * 256 + threadIdx.x;
    if (e >= E) return;
    int d = dst[e];
    int slot = atomicAdd(&g_cur[b][d], 1);
    g_csr[b][slot] = src[e];
}

// ---------------------------------------------------------------------------
// Gather aggregation over fp16 payload. 2 lanes per node (each 16B half-row),
// fp32 register accumulation, unroll-by-2 for MLP.
// PASS 0: agg1 = a1i + sum y[nbr];  h1f = relu(agg1);  h1h = fp16(h1f)
// PASS 1: agg2 = sum h1h[nbr]   (already relu'd)
// ---------------------------------------------------------------------------
template <int PASS>
__global__ void gather_kernel(int N) {
    int b = blockIdx.y;
    int t = threadIdx.x;
    int node = blockIdx.x * 128 + (t >> 1);
    if (node >= N) return;
    int h = t & 1;
    int start = g_part[b][node];
    int end = g_cur[b][node];
    const int* __restrict__ csr = g_csr[b];
    const __half* __restrict__ Y = PASS ? g_h1h[b] : g_yh[b];

    float2 c0 = make_float2(0.f, 0.f), c1 = c0, c2 = c0, c3 = c0;
    float2 d0 = c0, d1 = c0, d2 = c0, d3 = c0;
    int k = start;
    for (; k + 1 < end; k += 2) {
        int sA = __ldg(csr + k);
        int sB = __ldg(csr + k + 1);
        uint4 rA = *(const uint4*)(Y + ((size_t)sA << 4) + (h << 3));
        uint4 rB = *(const uint4*)(Y + ((size_t)sB << 4) + (h << 3));
        float2 fA0 = __half22float2(*(const __half2*)&rA.x);
        float2 fA1 = __half22float2(*(const __half2*)&rA.y);
        float2 fA2 = __half22float2(*(const __half2*)&rA.z);
        float2 fA3 = __half22float2(*(const __half2*)&rA.w);
        float2 fB0 = __half22float2(*(const __half2*)&rB.x);
        float2 fB1 = __half22float2(*(const __half2*)&rB.y);
        float2 fB2 = __half22float2(*(const __half2*)&rB.z);
        float2 fB3 = __half22float2(*(const __half2*)&rB.w);
        c0.x += fA0.x; c0.y += fA0.y; c1.x += fA1.x; c1.y += fA1.y;
        c2.x += fA2.x; c2.y += fA2.y; c3.x += fA3.x; c3.y += fA3.y;
        d0.x += fB0.x; d0.y += fB0.y; d1.x += fB1.x; d1.y += fB1.y;
        d2.x += fB2.x; d2.y += fB2.y; d3.x += fB3.x; d3.y += fB3.y;
    }
    if (k < end) {
        int s = __ldg(csr + k);
        uint4 raw = *(const uint4*)(Y + ((size_t)s << 4) + (h << 3));
        float2 f0 = __half22float2(*(const __half2*)&raw.x);
        float2 f1 = __half22float2(*(const __half2*)&raw.y);
        float2 f2 = __half22float2(*(const __half2*)&raw.z);
        float2 f3 = __half22float2(*(const __half2*)&raw.w);
        c0.x += f0.x; c0.y += f0.y; c1.x += f1.x; c1.y += f1.y;
        c2.x += f2.x; c2.y += f2.y; c3.x += f3.x; c3.y += f3.y;
    }
    c0.x += d0.x; c0.y += d0.y; c1.x += d1.x; c1.y += d1.y;
    c2.x += d2.x; c2.y += d2.y; c3.x += d3.x; c3.y += d3.y;

    size_t off = (size_t)node * 16 + (h << 3);
    if (PASS) {
        *(float4*)(g_agg2[b] + off) = make_float4(c0.x, c0.y, c1.x, c1.y);
        *(float4*)(g_agg2[b] + off + 4) = make_float4(c2.x, c2.y, c3.x, c3.y);
    } else {
        const float4* ip = (const float4*)(g_a1i[b] + off);
        float4 i0 = ip[0], i1 = ip[1];
        float4 v0 = make_float4(fmaxf(c0.x + i0.x, 0.f), fmaxf(c0.y + i0.y, 0.f),
                                fmaxf(c1.x + i0.z, 0.f), fmaxf(c1.y + i0.w, 0.f));
        float4 v1 = make_float4(fmaxf(c2.x + i1.x, 0.f), fmaxf(c2.y + i1.y, 0.f),
                                fmaxf(c3.x + i1.z, 0.f), fmaxf(c3.y + i1.w, 0.f));
        *(float4*)(g_h1f[b] + off) = v0;
        *(float4*)(g_h1f[b] + off + 4) = v1;
        __half2 q0 = __floats2half2_rn(v0.x, v0.y);
        __half2 q1 = __floats2half2_rn(v0.z, v0.w);
        __half2 q2 = __floats2half2_rn(v1.x, v1.y);
        __half2 q3 = __floats2half2_rn(v1.z, v1.w);
        uint4 hv;
        hv.x = *(unsigned*)&q0; hv.y = *(unsigned*)&q1;
        hv.z = *(unsigned*)&q2; hv.w = *(unsigned*)&q3;
        *(uint4*)(g_h1h[b] + off) = hv;
    }
}

// ---------------------------------------------------------------------------
// Fused tail: layer-2 convs (both branches) + MLP head, mol in registers.
// ---------------------------------------------------------------------------
__global__ __launch_bounds__(128)
void tail_kernel(const float* __restrict__ action,
                 const float* __restrict__ bp2, const float* __restrict__ bl2,
                 const float* __restrict__ b_in, const float* __restrict__ w_hid,
                 const float* __restrict__ b_hid, const float* __restrict__ w_out,
                 const float* __restrict__ b_out, float* __restrict__ out, int N) {
    __shared__ __align__(16) unsigned long long wsi[2][800];
    __shared__ __align__(16) float4 wst[1500];
    __shared__ __align__(16) float wh[700];
    __shared__ float bi[60];
    __shared__ float bs2[2][50];
    __shared__ __align__(16) float bh[12];
    __shared__ float wo[10];
    __shared__ float bo;
    int t = threadIdx.x;
    for (int i = t; i < 800; i += 128) {
        wsi[0][i] = g_wsi2[0][i];
        wsi[1][i] = g_wsi2[1][i];
    }
    for (int i = t; i < 1500; i += 128) wst[i] = g_wst[i];
    for (int i = t; i < 700; i += 128) wh[i] = w_hid[i];
    if (t < 60) bi[t] = b_in[t];
    if (t < 50) { bs2[0][t] = bp2[t]; bs2[1][t] = bl2[t]; }
    if (t < 10) { bh[t] = b_hid[t]; wo[t] = w_out[t]; }
    if (t == 0) bo = b_out[0];
    __syncthreads();

    int row = blockIdx.x * 128 + t;
    if (row >= N) return;

    unsigned long long molp[50];
#pragma unroll
    for (int b = 0; b < 2; b++) {
        unsigned long long ha[16];
        const float4* hp = (const float4*)(g_h1f[b] + (size_t)row * 16);
        const float4* ap = (const float4*)(g_agg2[b] + (size_t)row * 16);
#pragma unroll
        for (int q = 0; q < 4; q++) {
            float4 hv = hp[q], av = ap[q];
            ha[q * 4 + 0] = pk2(hv.x, av.x);
            ha[q * 4 + 1] = pk2(hv.y, av.y);
            ha[q * 4 + 2] = pk2(hv.z, av.z);
            ha[q * 4 + 3] = pk2(hv.w, av.w);
        }
        float prev = 0.f;
#pragma unroll 2
        for (int o = 0; o < 50; o++) {
            unsigned long long a0 = 0, a1 = 0;
#pragma unroll
            for (int k = 0; k < 16; k += 2) {
                a0 = fma2(ha[k], wsi[b][k * 50 + o], a0);
                a1 = fma2(ha[k + 1], wsi[b][(k + 1) * 50 + o], a1);
            }
            float2 p = upk2(a0), q = upk2(a1);
            float m = bs2[b][o] + ((p.x + p.y) + (q.x + q.y));
            if (o & 1) molp[(b * 50 + o) >> 1] = pk2(prev, m);
            else prev = m;
        }
    }

    unsigned long long pol2[5];
    const unsigned long long* bh2 = (const unsigned long long*)bh;
#pragma unroll
    for (int a = 0; a < 5; a++) pol2[a] = bh2[a];

#pragma unroll 1
    for (int o = 0; o < 60; o++) {
        const ulonglong2* wr = (const ulonglong2*)(wst + o * 25);
        unsigned long long a0 = 0, a1 = 0;
#pragma unroll
        for (int kk = 0; kk < 25; kk++) {
            ulonglong2 wv = wr[kk];
            a0 = fma2(molp[2 * kk], wv.x, a0);
            a1 = fma2(molp[2 * kk + 1], wv.y, a1);
        }
        float2 p = upk2(a0), q = upk2(a1);
        float f = fmaxf(bi[o] + ((p.x + p.y) + (q.x + q.y)), 0.f);
        unsigned long long f2 = pk2(f, f);
        const unsigned long long* whp = (const unsigned long long*)(wh + o * 10);
#pragma unroll
        for (int a = 0; a < 5; a++) pol2[a] = fma2(f2, whp[a], pol2[a]);
    }

    const unsigned long long* a2 = (const unsigned long long*)(action + (size_t)row * 10);
#pragma unroll
    for (int jj = 0; jj < 5; jj++) {
        float2 ap = upk2(a2[jj]);
        unsigned long long u = pk2(ap.x, ap.x);
        unsigned long long v = pk2(ap.y, ap.y);
        const unsigned long long* w1 = (const unsigned long long*)(wh + (60 + 2 * jj) * 10);
        const unsigned long long* w2p = (const unsigned long long*)(wh + (61 + 2 * jj) * 10);
#pragma unroll
        for (int a = 0; a < 5; a++) {
            pol2[a] = fma2(u, w1[a], pol2[a]);
            pol2[a] = fma2(v, w2p[a], pol2[a]);
        }
    }

    float res = bo;
#pragma unroll
    for (int a = 0; a < 5; a++) {
        float2 p = upk2(pol2[a]);
        res = fmaf(fmaxf(p.x, 0.f), wo[2 * a], res);
        res = fmaf(fmaxf(p.y, 0.f), wo[2 * a + 1], res);
    }
    out[row] = res;
}

// ---------------------------------------------------------------------------
// Side stream + fork/join events (created once at load; streams/events are
// not device-memory allocations). Fallback: everything on the default stream.
// ---------------------------------------------------------------------------
static cudaStream_t g_s1 = 0;
static cudaEvent_t g_evRoot = 0, g_evCsr = 0;
static bool g_forkOk = false;
namespace {
struct ForkInit {
    ForkInit() {
        bool ok = true;
        ok &= (cudaStreamCreateWithFlags(&g_s1, cudaStreamNonBlocking) == cudaSuccess);
        ok &= (cudaEventCreateWithFlags(&g_evRoot, cudaEventDisableTiming) == cudaSuccess);
        ok &= (cudaEventCreateWithFlags(&g_evCsr, cudaEventDisableTiming) == cudaSuccess);
        g_forkOk = ok;
    }
};
static ForkInit g_forkInit;
}  // namespace

// ---------------------------------------------------------------------------
extern "C" void kernel_launch(void* const* d_in, const int* in_sizes, int n_in,
                              void* d_out, int out_size) {
    const float* px = (const float*)d_in[0];
    const int*   pe = (const int*)d_in[1];
    const float* lx = (const float*)d_in[2];
    const int*   le = (const int*)d_in[3];
    const float* action = (const float*)d_in[4];
    const float* wp1s = (const float*)d_in[5];
    const float* wp1n = (const float*)d_in[6];
    const float* bp1  = (const float*)d_in[7];
    const float* wp2s = (const float*)d_in[8];
    const float* wp2n = (const float*)d_in[9];
    const float* bp2  = (const float*)d_in[10];
    const float* wl1s = (const float*)d_in[11];
    const float* wl1n = (const float*)d_in[12];
    const float* bl1  = (const float*)d_in[13];
    const float* wl2s = (const float*)d_in[14];
    const float* wl2n = (const float*)d_in[15];
    const float* bl2  = (const float*)d_in[16];
    const float* w_in  = (const float*)d_in[17];
    const float* b_in  = (const float*)d_in[18];
    const float* w_hid = (const float*)d_in[19];
    const float* b_hid = (const float*)d_in[20];
    const float* w_out = (const float*)d_in[21];
    const float* b_out = (const float*)d_in[22];
    float* out = (float*)d_out;

    int N = in_sizes[0] / 128;
    int E0 = in_sizes[1] / 2;
    int E1 = in_sizes[3] / 2;
    int Em = (E0 > E1) ? E0 : E1;
    int nb = (N + 1023) / 1024;

    cudaStream_t sc = g_forkOk ? g_s1 : (cudaStream_t)0;  // CSR-arm stream
    if (g_forkOk) {
        cudaEventRecord(g_evRoot, 0);
        cudaStreamWaitEvent(g_s1, g_evRoot, 0);
    }

    // ---- dense arm (capture stream) -------------------------------------
    const int proj_smem = (128 * 129 + 128 * 32) * (int)sizeof(float);
    cudaFuncSetAttribute(proj_kernel, cudaFuncAttributeMaxDynamicSharedMemorySize,
                         proj_smem);
    dim3 gp((N + 127) / 128, 2);
    proj_kernel<<<gp, 256, proj_smem>>>(px, lx, wp1s, wl1s, wp1n, wl1n, bp1, bl1, N);

    // ---- CSR arm (side stream) -------------------------------------------
    prep_kernel<<<((2 * NN / 4) + 255) / 256, 256, 0, sc>>>(w_in, wp2s, wp2n,
                                                            wl2s, wl2n);
    dim3 ge((Em + 255) / 256, 2);
    count_kernel<<<ge, 256, 0, sc>>>(pe + E0, le + E1, E0, E1);

    dim3 gs(nb, 2);
    scan1_kernel<<<gs, 256, 0, sc>>>(N);
    scan2_kernel<<<2, 128, 0, sc>>>(nb);

    dim3 gf((N + 255) / 256, 2);
    fixup_kernel<<<gf, 256, 0, sc>>>(N);

    scatter_kernel<<<ge, 256, 0, sc>>>(pe, pe + E0, le, le + E1, E0, E1);

    if (g_forkOk) {
        cudaEventRecord(g_evCsr, g_s1);
        cudaStreamWaitEvent(0, g_evCsr, 0);
    }

    // ---- joined: gathers + tail (capture stream) -------------------------
    dim3 gg((N + 127) / 128, 2);
    gather_kernel<0><<<gg, 256>>>(N);
    gather_kernel<1><<<gg, 256>>>(N);

    tail_kernel<<<(N + 127) / 128, 128>>>(action, bp2, bl2, b_in, w_hid, b_hid,
                                          w_out, b_out, out, N);
}